// round 14
// baseline (speedup 1.0000x reference)
#include <cuda_runtime.h>
#include <cuda_bf16.h>
#include <math.h>

// Problem constants (B=1, N=50000, E=600000, H=128, ET=8)
#define NMAX 50000
#define EMAX 600000
#define HDIM 128
#define ETMAX 8

// ---------------- scratch ----------------
__device__ float g_Qp[NMAX * HDIM];     // Q' = scale*q @ Wk^T
__device__ float g_hagg[NMAX * HDIM];   // sum of ex * hidden[src]
__device__ float g_QEK[NMAX * ETMAX];   // scale*q.(EK[ty]+bk) + ebias[ty]
__device__ float g_exsum[NMAX * ETMAX];
__device__ float g_wex[NMAX * ETMAX];
__device__ float g_EK[ETMAX * HDIM];
__device__ float g_EV[ETMAX * HDIM];
__device__ float g_ebias[ETMAX];
__device__ float g_Wp[HDIM * HDIM];     // scale * Wq @ Wk^T (fp32 stage)
__device__ float g_bp[HDIM];
__device__ float g_WqEK[HDIM * ETMAX];
__device__ float g_cbias[ETMAX];
__device__ float g_WvW1[HDIM * HDIM];   // Wv @ W1[128:256]
__device__ float g_EVW[ETMAX * HDIM];   // EV @ W1[128:256]
__device__ float g_b1t[HDIM];

// pre-split bf16 hi/lo operands (k-loop is conversion-free for these)
__device__ __nv_bfloat16 g_Ahi[NMAX * HDIM], g_Alo[NMAX * HDIM];   // hagg*invsm
__device__ __nv_bfloat16 g_Thi[NMAX * HDIM], g_Tlo[NMAX * HDIM];   // FFN1 out
__device__ __nv_bfloat16 g_WpH[HDIM * HDIM], g_WpL[HDIM * HDIM];
__device__ __nv_bfloat16 g_W1H[2 * HDIM * HDIM], g_W1L[2 * HDIM * HDIM]; // W1top ⊕ WvW1
__device__ __nv_bfloat16 g_W2H[HDIM * HDIM], g_W2L[HDIM * HDIM];
__device__ __nv_bfloat16 g_QEH[HDIM * ETMAX], g_QEL[HDIM * ETMAX];

#define SCALE 0.08838834764831845f  // 1/sqrt(128)

// ---------------- helpers ----------------
__device__ __forceinline__ unsigned pack_bf16(__nv_bfloat16 lo_k, __nv_bfloat16 hi_k) {
    return ((unsigned)__bfloat16_as_ushort(hi_k) << 16) | (unsigned)__bfloat16_as_ushort(lo_k);
}
__device__ __forceinline__ void split_bf16(float v, __nv_bfloat16& hi, __nv_bfloat16& lo) {
    hi = __float2bfloat16(v);
    lo = __float2bfloat16(v - __bfloat162float(hi));
}
__device__ __forceinline__ void mma_bf16(float c[4], const unsigned a[4], const unsigned b[2]) {
    asm volatile(
        "mma.sync.aligned.m16n8k16.row.col.f32.bf16.bf16.f32 "
        "{%0,%1,%2,%3}, {%4,%5,%6,%7}, {%8,%9}, {%0,%1,%2,%3};"
        : "+f"(c[0]), "+f"(c[1]), "+f"(c[2]), "+f"(c[3])
        : "r"(a[0]), "r"(a[1]), "r"(a[2]), "r"(a[3]), "r"(b[0]), "r"(b[1]));
}
__device__ __forceinline__ void ldsm_x4(unsigned r[4], unsigned addr) {
    asm volatile("ldmatrix.sync.aligned.m8n8.x4.shared.b16 {%0,%1,%2,%3}, [%4];"
                 : "=r"(r[0]), "=r"(r[1]), "=r"(r[2]), "=r"(r[3]) : "r"(addr));
}
__device__ __forceinline__ void ldsm_x4_t(unsigned r[4], unsigned addr) {
    asm volatile("ldmatrix.sync.aligned.m8n8.x4.trans.shared.b16 {%0,%1,%2,%3}, [%4];"
                 : "=r"(r[0]), "=r"(r[1]), "=r"(r[2]), "=r"(r[3]) : "r"(addr));
}

// ---------------- init: hagg=0, exsum=0 ----------------
__global__ void init_kernel(int Nn) {
    int i = blockIdx.x * blockDim.x + threadIdx.x;
    if (i < Nn * HDIM) g_hagg[i] = 0.0f;
    if (i < Nn * ETMAX) g_exsum[i] = 0.0f;
}

// ---------------- EK/EV/ebias: block per edge type ----------------
__global__ void etype_v2(const float* __restrict__ edge_emb,
                         const float* __restrict__ Wk,
                         const float* __restrict__ Wv,
                         const float* __restrict__ Web,
                         const float* __restrict__ beb) {
    __shared__ float eh[HDIM];
    int ty = blockIdx.x, j = threadIdx.x;
    eh[j] = edge_emb[ty * HDIM + j];
    __syncthreads();
    float k0 = 0, k1 = 0, k2 = 0, k3 = 0;
    float v0 = 0, v1 = 0, v2 = 0, v3 = 0;
#pragma unroll 8
    for (int k = 0; k < HDIM; k += 4) {
        k0 = fmaf(eh[k],     Wk[(k)     * HDIM + j], k0);
        k1 = fmaf(eh[k + 1], Wk[(k + 1) * HDIM + j], k1);
        k2 = fmaf(eh[k + 2], Wk[(k + 2) * HDIM + j], k2);
        k3 = fmaf(eh[k + 3], Wk[(k + 3) * HDIM + j], k3);
        v0 = fmaf(eh[k],     Wv[(k)     * HDIM + j], v0);
        v1 = fmaf(eh[k + 1], Wv[(k + 1) * HDIM + j], v1);
        v2 = fmaf(eh[k + 2], Wv[(k + 2) * HDIM + j], v2);
        v3 = fmaf(eh[k + 3], Wv[(k + 3) * HDIM + j], v3);
    }
    g_EK[ty * HDIM + j] = (k0 + k1) + (k2 + k3);
    g_EV[ty * HDIM + j] = (v0 + v1) + (v2 + v3);
    if (j == 0) {
        float a0 = 0, a1 = 0, a2 = 0, a3 = 0;
        for (int k = 0; k < HDIM; k += 4) {
            a0 = fmaf(eh[k], Web[k], a0);
            a1 = fmaf(eh[k + 1], Web[k + 1], a1);
            a2 = fmaf(eh[k + 2], Web[k + 2], a2);
            a3 = fmaf(eh[k + 3], Web[k + 3], a3);
        }
        g_ebias[ty] = (a0 + a1) + (a2 + a3) + beb[0];
    }
}

// ---------------- combined small-matrix precompute v2: row per block ----------------
__global__ void combo_v2(const float* __restrict__ Wq, const float* __restrict__ bq,
                         const float* __restrict__ Wk, const float* __restrict__ bk,
                         const float* __restrict__ Wv, const float* __restrict__ bv,
                         const float* __restrict__ W1, const float* __restrict__ b1) {
    __shared__ float row[HDIM];
    int b = blockIdx.x, t = threadIdx.x;
    const float* W1b = W1 + HDIM * HDIM;  // rows 128..255

    if (b < 128 || b == 256) {
        row[t] = (b < 128) ? Wq[b * HDIM + t] : bq[t];
        __syncthreads();
        const float4* wr = (const float4*)(Wk + t * HDIM);
        float a0 = 0, a1 = 0, a2 = 0, a3 = 0;
#pragma unroll 8
        for (int j = 0; j < 32; j++) {
            float4 w = wr[j];
            float4 q = *(const float4*)&row[j * 4];
            a0 = fmaf(q.x, w.x, a0);
            a1 = fmaf(q.y, w.y, a1);
            a2 = fmaf(q.z, w.z, a2);
            a3 = fmaf(q.w, w.w, a3);
        }
        float s = ((a0 + a1) + (a2 + a3)) * SCALE;
        if (b < 128) g_Wp[b * HDIM + t] = s;
        else g_bp[t] = s;
    } else if (b < 256 || b == 257 || (b >= 258 && b < 266)) {
        if (b < 256) row[t] = Wv[(b - 128) * HDIM + t];
        else if (b == 257) row[t] = bv[t];
        else row[t] = g_EV[(b - 258) * HDIM + t];
        __syncthreads();
        float a0 = 0, a1 = 0, a2 = 0, a3 = 0;
#pragma unroll 8
        for (int k = 0; k < HDIM; k += 4) {
            a0 = fmaf(row[k],     W1b[(k)     * HDIM + t], a0);
            a1 = fmaf(row[k + 1], W1b[(k + 1) * HDIM + t], a1);
            a2 = fmaf(row[k + 2], W1b[(k + 2) * HDIM + t], a2);
            a3 = fmaf(row[k + 3], W1b[(k + 3) * HDIM + t], a3);
        }
        float s = (a0 + a1) + (a2 + a3);
        if (b < 256) g_WvW1[(b - 128) * HDIM + t] = s;
        else if (b == 257) g_b1t[t] = s + b1[t];
        else g_EVW[(b - 258) * HDIM + t] = s;
    } else if (b == 266) {
        row[t] = bk[t];
        __syncthreads();
        float acc[ETMAX] = {};
        const float4* qr = (const float4*)(Wq + t * HDIM);
#pragma unroll 4
        for (int j4 = 0; j4 < 32; j4++) {
            float4 q = qr[j4];
            float4 bb = *(const float4*)&row[j4 * 4];
#pragma unroll
            for (int ty = 0; ty < ETMAX; ty++) {
                float4 ek = *(const float4*)&g_EK[ty * HDIM + j4 * 4];
                acc[ty] += q.x * (ek.x + bb.x) + q.y * (ek.y + bb.y)
                         + q.z * (ek.z + bb.z) + q.w * (ek.w + bb.w);
            }
        }
#pragma unroll
        for (int ty = 0; ty < ETMAX; ty++) g_WqEK[t * ETMAX + ty] = acc[ty] * SCALE;
    } else {
        if (t < ETMAX) {
            float a0 = 0, a1 = 0, a2 = 0, a3 = 0;
            for (int j = 0; j < HDIM; j += 4) {
                a0 = fmaf(bq[j],     g_EK[t * HDIM + j]     + bk[j],     a0);
                a1 = fmaf(bq[j + 1], g_EK[t * HDIM + j + 1] + bk[j + 1], a1);
                a2 = fmaf(bq[j + 2], g_EK[t * HDIM + j + 2] + bk[j + 2], a2);
                a3 = fmaf(bq[j + 3], g_EK[t * HDIM + j + 3] + bk[j + 3], a3);
            }
            g_cbias[t] = ((a0 + a1) + (a2 + a3)) * SCALE + g_ebias[t];
        }
    }
}

// ---------------- weight bf16 split (after combo) ----------------
__global__ void wconvert_kernel(const float* __restrict__ W1, const float* __restrict__ W2) {
    int idx = blockIdx.x * blockDim.x + threadIdx.x;
    float v;
    __nv_bfloat16 *dh, *dl;
    int o;
    if (idx < 16384) { v = g_Wp[idx]; dh = g_WpH; dl = g_WpL; o = idx; }
    else if (idx < 49152) {
        o = idx - 16384;
        int r = o >> 7, n = o & 127;
        v = (r < HDIM) ? W1[r * HDIM + n] : g_WvW1[(r - HDIM) * HDIM + n];
        dh = g_W1H; dl = g_W1L;
    }
    else if (idx < 65536) { o = idx - 49152; v = W2[o]; dh = g_W2H; dl = g_W2L; }
    else if (idx < 66560) { o = idx - 65536; v = g_WqEK[o]; dh = g_QEH; dl = g_QEL; }
    else return;
    __nv_bfloat16 hi, lo;
    split_bf16(v, hi, lo);
    dh[o] = hi; dl[o] = lo;
}

// ---------------- bf16x2 tensor-core GEMM, BK=64, ldmatrix, pre-split B ----------------
// MODE 1: Q' GEMM (A=hidden fp32-split) + QEK side-output.
// MODE 2: FFN1 (A k<128: hidden fp32-split; k>=128: pre-split AGG; W=g_W1 256 rows;
//         +wex@EVW, silu) -> writes T as bf16 hi/lo.
// MODE 3: FFN2 (A=T pre-split) + residual + layernorm -> out.
constexpr int BM = 64, BN = 128, BK = 64;
constexpr int LDK = BK + 8;   // 72 bf16 -> 144 B rows
constexpr int LDN = BN + 8;   // 136 bf16 -> 272 B rows

constexpr int OFF_A_HI = 0;                       // bf16 [64][72] = 9216
constexpr int OFF_A_LO = 9216;
constexpr int OFF_B_HI = 18432;                   // bf16 [64][136] = 17408
constexpr int OFF_B_LO = 35840;
constexpr int OFF_QE_HI = 53248;                  // bf16 [64][8] = 1024 (MODE 1)
constexpr int OFF_QE_LO = 54272;
constexpr int OFF_EVW  = 53248;                   // float [8][128] = 4096 (MODE 2)
constexpr int OFF_WEX  = 57344;                   // float [64][8] = 2048 (MODE 2)
constexpr int SMEM_BYTES = 61440;
// MODE 3 epilogue aliases [0, 32768) as float Us[64][128].

template <int KDIM, int MODE>
__global__ void __launch_bounds__(256, 2)
mma_gemm(const float* __restrict__ A,
         const __nv_bfloat16* __restrict__ AH, const __nv_bfloat16* __restrict__ AL,
         const __nv_bfloat16* __restrict__ WH, const __nv_bfloat16* __restrict__ WL,
         const float* __restrict__ bias,
         float* __restrict__ C,
         const float* __restrict__ hidden, const float* __restrict__ gamma,
         const float* __restrict__ beta,
         int M) {
    extern __shared__ char dynsmem[];
    __nv_bfloat16* As_hi = (__nv_bfloat16*)(dynsmem + OFF_A_HI);
    __nv_bfloat16* As_lo = (__nv_bfloat16*)(dynsmem + OFF_A_LO);
    __nv_bfloat16* Bs_hi = (__nv_bfloat16*)(dynsmem + OFF_B_HI);
    __nv_bfloat16* Bs_lo = (__nv_bfloat16*)(dynsmem + OFF_B_LO);
    __nv_bfloat16* QE_hi = (__nv_bfloat16*)(dynsmem + OFF_QE_HI);
    __nv_bfloat16* QE_lo = (__nv_bfloat16*)(dynsmem + OFF_QE_LO);
    float* evws = (float*)(dynsmem + OFF_EVW);
    float* wexs = (float*)(dynsmem + OFF_WEX);
    float* Us   = (float*)dynsmem;

    const int t = threadIdx.x;
    const int block_m = blockIdx.x * BM;
    const int lane = t & 31;
    const int wid = t >> 5;
    const int warp_m = (wid >> 2) * 32;
    const int warp_n = (wid & 3) * 32;
    const int lg = lane >> 2;
    const int lt = lane & 3;

    if (MODE == 2) {
        {
            int ty = t >> 5, n4 = (t & 31) * 4;
            *(float4*)&evws[ty * HDIM + n4] = *(const float4*)(g_EVW + ty * HDIM + n4);
        }
        if (t < 128) {
            int r = t >> 1, half = t & 1;
            int gm = block_m + r;
            float4 v = make_float4(0.f, 0.f, 0.f, 0.f);
            if (gm < M) v = *(const float4*)(g_wex + gm * ETMAX + half * 4);
            *(float4*)&wexs[r * ETMAX + half * 4] = v;
        }
    }

    // ---- ldmatrix per-lane base addresses ----
    unsigned sb = (unsigned)__cvta_generic_to_shared(dynsmem);
    unsigned a_addr0 = sb + OFF_A_HI + (warp_m + (lane & 15)) * (LDK * 2) + ((lane >> 4) * 8) * 2;
    unsigned a_addr1 = a_addr0 + 16 * (LDK * 2);
    unsigned b_row = ((lane & 7) + ((lane >> 3) & 1) * 8);
    unsigned b_addr0 = sb + OFF_B_HI + b_row * (LDN * 2) + (warp_n + (lane >> 4) * 8) * 2;
    unsigned b_addr1 = b_addr0 + 16 * 2;
    constexpr unsigned A_LO_D = OFF_A_LO - OFF_A_HI;
    constexpr unsigned B_LO_D = OFF_B_LO - OFF_B_HI;

    float acc[2][4][4];
#pragma unroll
    for (int mi = 0; mi < 2; mi++)
#pragma unroll
        for (int ni = 0; ni < 4; ni++)
#pragma unroll
            for (int r = 0; r < 4; r++) acc[mi][ni][r] = 0.0f;

    float acc_q[2][4];
    if (MODE == 1) {
#pragma unroll
        for (int mi = 0; mi < 2; mi++)
#pragma unroll
            for (int r = 0; r < 4; r++) acc_q[mi][r] = 0.0f;
    }

    for (int k0 = 0; k0 < KDIM; k0 += BK) {
        // ---- A tile ----
        if (MODE == 3 || (MODE == 2 && k0 >= HDIM)) {
            // pre-split bf16 source: 64 rows x 64 bf16 per buffer = 512 16B chunks
            const __nv_bfloat16* srcH = (MODE == 3) ? AH : AH;
            const __nv_bfloat16* srcL = (MODE == 3) ? AL : AL;
            int colbase = (MODE == 3) ? k0 : (k0 - HDIM);
#pragma unroll
            for (int i = 0; i < 2; i++) {
                int idx = t + i * 256;
                int m = idx >> 3;
                int k8 = (idx & 7) * 8;
                int gm = block_m + m;
                uint4 vh = make_uint4(0, 0, 0, 0), vl = make_uint4(0, 0, 0, 0);
                if (gm < M) {
                    vh = *(const uint4*)(srcH + (size_t)gm * HDIM + colbase + k8);
                    vl = *(const uint4*)(srcL + (size_t)gm * HDIM + colbase + k8);
                }
                *(uint4*)&As_hi[m * LDK + k8] = vh;
                *(uint4*)&As_lo[m * LDK + k8] = vl;
            }
        } else {
            // fp32 source (hidden), split in-kernel
#pragma unroll
            for (int i = 0; i < 4; i++) {
                int idx = t + i * 256;
                int m = idx >> 4;
                int k4 = (idx & 15) * 4;
                int gm = block_m + m;
                float4 v = make_float4(0.f, 0.f, 0.f, 0.f);
                if (gm < M) v = *(const float4*)(A + (size_t)gm * HDIM + k0 + k4);
                __nv_bfloat16 hx, lx, hy, ly, hz, lz, hw, lw;
                split_bf16(v.x, hx, lx); split_bf16(v.y, hy, ly);
                split_bf16(v.z, hz, lz); split_bf16(v.w, hw, lw);
                *(uint2*)&As_hi[m * LDK + k4] = make_uint2(pack_bf16(hx, hy), pack_bf16(hz, hw));
                *(uint2*)&As_lo[m * LDK + k4] = make_uint2(pack_bf16(lx, ly), pack_bf16(lz, lw));
            }
        }
        // ---- B tile: pre-split bf16, pure copy (64 x 128 bf16 = 1024 chunks/buffer) ----
#pragma unroll
        for (int i = 0; i < 4; i++) {
            int idx = t + i * 256;
            int kk = idx >> 4;
            int n8 = (idx & 15) * 8;
            size_t off = (size_t)(k0 + kk) * BN + n8;
            *(uint4*)&Bs_hi[kk * LDN + n8] = *(const uint4*)(WH + off);
            *(uint4*)&Bs_lo[kk * LDN + n8] = *(const uint4*)(WL + off);
        }
        // ---- WqEK tile (MODE 1): 64 x 8 bf16 = 64 chunks/buffer ----
        if (MODE == 1 && t < 128) {
            int h = t >> 6;     // 0 = hi, 1 = lo
            int c = t & 63;     // row within tile
            const __nv_bfloat16* s = (h ? g_QEL : g_QEH) + (size_t)(k0 + c) * ETMAX;
            __nv_bfloat16* d = (h ? QE_lo : QE_hi) + c * 8;
            *(uint4*)d = *(const uint4*)s;
        }
        __syncthreads();

#pragma unroll
        for (int ks = 0; ks < BK; ks += 16) {
            unsigned ah[2][4], al[2][4], bh[4][2], bl[4][2];
            ldsm_x4(ah[0], a_addr0 + ks * 2);
            ldsm_x4(ah[1], a_addr1 + ks * 2);
            ldsm_x4(al[0], a_addr0 + A_LO_D + ks * 2);
            ldsm_x4(al[1], a_addr1 + A_LO_D + ks * 2);
            {
                unsigned q[4];
                ldsm_x4_t(q, b_addr0 + ks * (LDN * 2));
                bh[0][0] = q[0]; bh[0][1] = q[1]; bh[1][0] = q[2]; bh[1][1] = q[3];
                ldsm_x4_t(q, b_addr1 + ks * (LDN * 2));
                bh[2][0] = q[0]; bh[2][1] = q[1]; bh[3][0] = q[2]; bh[3][1] = q[3];
                ldsm_x4_t(q, b_addr0 + B_LO_D + ks * (LDN * 2));
                bl[0][0] = q[0]; bl[0][1] = q[1]; bl[1][0] = q[2]; bl[1][1] = q[3];
                ldsm_x4_t(q, b_addr1 + B_LO_D + ks * (LDN * 2));
                bl[2][0] = q[0]; bl[2][1] = q[1]; bl[3][0] = q[2]; bl[3][1] = q[3];
            }
#pragma unroll
            for (int mi = 0; mi < 2; mi++)
#pragma unroll
                for (int ni = 0; ni < 4; ni++) {
                    mma_bf16(acc[mi][ni], ah[mi], bl[ni]);
                    mma_bf16(acc[mi][ni], al[mi], bh[ni]);
                    mma_bf16(acc[mi][ni], ah[mi], bh[ni]);
                }
            if (MODE == 1 && warp_n == 0) {
                unsigned qh[2], ql[2];
                int k = ks + lt * 2;
                qh[0] = pack_bf16(QE_hi[k * 8 + lg], QE_hi[(k + 1) * 8 + lg]);
                qh[1] = pack_bf16(QE_hi[(k + 8) * 8 + lg], QE_hi[(k + 9) * 8 + lg]);
                ql[0] = pack_bf16(QE_lo[k * 8 + lg], QE_lo[(k + 1) * 8 + lg]);
                ql[1] = pack_bf16(QE_lo[(k + 8) * 8 + lg], QE_lo[(k + 9) * 8 + lg]);
#pragma unroll
                for (int mi = 0; mi < 2; mi++) {
                    mma_bf16(acc_q[mi], ah[mi], ql);
                    mma_bf16(acc_q[mi], al[mi], qh);
                    mma_bf16(acc_q[mi], ah[mi], qh);
                }
            }
        }
        __syncthreads();
    }

    // ---- epilogue ----
    if (MODE == 1) {
#pragma unroll
        for (int mi = 0; mi < 2; mi++)
#pragma unroll
            for (int ni = 0; ni < 4; ni++) {
                int n = warp_n + ni * 8 + lt * 2;
                float b0 = bias[n], b1 = bias[n + 1];
#pragma unroll
                for (int h = 0; h < 2; h++) {
                    int gm = block_m + warp_m + mi * 16 + lg + h * 8;
                    if (gm >= M) continue;
                    *(float2*)(C + (size_t)gm * BN + n) =
                        make_float2(acc[mi][ni][2 * h] + b0, acc[mi][ni][2 * h + 1] + b1);
                }
            }
        if (warp_n == 0) {
            float cb0 = g_cbias[lt * 2], cb1 = g_cbias[lt * 2 + 1];
#pragma unroll
            for (int mi = 0; mi < 2; mi++)
#pragma unroll
                for (int h = 0; h < 2; h++) {
                    int gm = block_m + warp_m + mi * 16 + lg + h * 8;
                    if (gm >= M) continue;
                    *(float2*)(g_QEK + gm * ETMAX + lt * 2) =
                        make_float2(acc_q[mi][2 * h] + cb0, acc_q[mi][2 * h + 1] + cb1);
                }
        }
    } else if (MODE == 2) {
#pragma unroll
        for (int mi = 0; mi < 2; mi++)
#pragma unroll
            for (int ni = 0; ni < 4; ni++) {
                int n = warp_n + ni * 8 + lt * 2;
                float b0 = bias[n], b1 = bias[n + 1];
#pragma unroll
                for (int h = 0; h < 2; h++) {
                    int r = warp_m + mi * 16 + lg + h * 8;
                    int gm = block_m + r;
                    if (gm >= M) continue;
                    float v0 = acc[mi][ni][2 * h] + b0;
                    float v1 = acc[mi][ni][2 * h + 1] + b1;
#pragma unroll
                    for (int ty = 0; ty < ETMAX; ty++) {
                        float wv = wexs[r * ETMAX + ty];
                        v0 = fmaf(wv, evws[ty * HDIM + n], v0);
                        v1 = fmaf(wv, evws[ty * HDIM + n + 1], v1);
                    }
                    v0 = v0 / (1.0f + expf(-v0));
                    v1 = v1 / (1.0f + expf(-v1));
                    __nv_bfloat16 h0, l0, h1, l1;
                    split_bf16(v0, h0, l0);
                    split_bf16(v1, h1, l1);
                    *(unsigned*)&g_Thi[(size_t)gm * HDIM + n] = pack_bf16(h0, h1);
                    *(unsigned*)&g_Tlo[(size_t)gm * HDIM + n] = pack_bf16(l0, l1);
                }
            }
    } else {
        // FFN2 + residual + layernorm fused
#pragma unroll
        for (int mi = 0; mi < 2; mi++)
#pragma unroll
            for (int ni = 0; ni < 4; ni++) {
                int n = warp_n + ni * 8 + lt * 2;
                float b0 = bias[n], b1 = bias[n + 1];
#pragma unroll
                for (int h = 0; h < 2; h++) {
                    int r = warp_m + mi * 16 + lg + h * 8;
                    *(float2*)&Us[r * HDIM + n] =
                        make_float2(acc[mi][ni][2 * h] + b0, acc[mi][ni][2 * h + 1] + b1);
                }
            }
        __syncthreads();
        float4 gm4 = ((const float4*)gamma)[lane];
        float4 bt4 = ((const float4*)beta)[lane];
#pragma unroll
        for (int j = 0; j < 8; j++) {
            int r = wid * 8 + j;
            int gm = block_m + r;
            if (gm >= M) continue;
            float4 u = *(const float4*)&Us[r * HDIM + lane * 4];
            float4 hh = *(const float4*)(hidden + (size_t)gm * HDIM + lane * 4);
            float x0 = hh.x + u.x, x1 = hh.y + u.y, x2 = hh.z + u.z, x3 = hh.w + u.w;
            float sum = x0 + x1 + x2 + x3;
#pragma unroll
            for (int o = 16; o; o >>= 1) sum += __shfl_xor_sync(0xffffffffu, sum, o);
            float mu = sum * (1.0f / 128.0f);
            float d0 = x0 - mu, d1 = x1 - mu, d2 = x2 - mu, d3 = x3 - mu;
            float vs = d0 * d0 + d1 * d1 + d2 * d2 + d3 * d3;
#pragma unroll
            for (int o = 16; o; o >>= 1) vs += __shfl_xor_sync(0xffffffffu, vs, o);
            float inv = rsqrtf(vs * (1.0f / 128.0f) + 1e-5f);
            float4 o4;
            o4.x = d0 * inv * gm4.x + bt4.x;
            o4.y = d1 * inv * gm4.y + bt4.y;
            o4.z = d2 * inv * gm4.z + bt4.z;
            o4.w = d3 * inv * gm4.w + bt4.w;
            *(float4*)(C + (size_t)gm * HDIM + lane * 4) = o4;
        }
    }
}

// ---------------- fused edge pass (warp per edge) ----------------
__global__ void edge_fused_kernel(const float* __restrict__ hidden,
                                  const int* __restrict__ src, const int* __restrict__ tgt,
                                  const int* __restrict__ etype, int E) {
    int e = blockIdx.x * 8 + (threadIdx.x >> 5);
    if (e >= E) return;
    int lane = threadIdx.x & 31;
    int s = src[e], g = tgt[e], ty = etype[e];
    float4 q = ((const float4*)(g_Qp + (size_t)g * HDIM))[lane];
    float4 h = ((const float4*)(hidden + (size_t)s * HDIM))[lane];
    float d = q.x * h.x + q.y * h.y + q.z * h.z + q.w * h.w;
#pragma unroll
    for (int o = 16; o; o >>= 1) d += __shfl_xor_sync(0xffffffffu, d, o);
    float ex = expf(d + g_QEK[g * ETMAX + ty]);
    if (lane == 0) atomicAdd(&g_exsum[g * ETMAX + ty], ex);
    float* dst = g_hagg + (size_t)g * HDIM + lane * 4;
    asm volatile("red.global.add.v4.f32 [%0], {%1, %2, %3, %4};"
                 :: "l"(dst), "f"(ex * h.x), "f"(ex * h.y), "f"(ex * h.z), "f"(ex * h.w)
                 : "memory");
}

// ---------------- normalize: wex + AGG bf16 split (warp per node) ----------------
__global__ void normalize_kernel(int Nn) {
    int n = blockIdx.x * 8 + (threadIdx.x >> 5);
    if (n >= Nn) return;
    int lane = threadIdx.x & 31;
    float ex = (lane < ETMAX) ? g_exsum[n * ETMAX + lane] : 0.0f;
    float s = ex;
#pragma unroll
    for (int o = 4; o; o >>= 1) s += __shfl_xor_sync(0xffffffffu, s, o);
    s = __shfl_sync(0xffffffffu, s, 0);
    float inv = (s > 0.0f) ? (1.0f / s) : 0.0f;
    if (lane < ETMAX) g_wex[n * ETMAX + lane] = ex * inv;
    float4 v = ((const float4*)(g_hagg + (size_t)n * HDIM))[lane];
    v.x *= inv; v.y *= inv; v.z *= inv; v.w *= inv;
    __nv_bfloat16 hx, lx, hy, ly, hz, lz, hw, lw;
    split_bf16(v.x, hx, lx); split_bf16(v.y, hy, ly);
    split_bf16(v.z, hz, lz); split_bf16(v.w, hw, lw);
    ((uint2*)(g_Ahi + (size_t)n * HDIM))[lane] = make_uint2(pack_bf16(hx, hy), pack_bf16(hz, hw));
    ((uint2*)(g_Alo + (size_t)n * HDIM))[lane] = make_uint2(pack_bf16(lx, ly), pack_bf16(lz, lw));
}

// ---------------- launch ----------------
extern "C" void kernel_launch(void* const* d_in, const int* in_sizes, int n_in,
                              void* d_out, int out_size) {
    const float* hidden   = (const float*)d_in[0];
    const int*   edge_idx = (const int*)d_in[1];
    const int*   etype    = (const int*)d_in[2];
    const float* edge_emb = (const float*)d_in[3];
    const float* Wq = (const float*)d_in[4];
    const float* bq = (const float*)d_in[5];
    const float* Wk = (const float*)d_in[6];
    const float* bk = (const float*)d_in[7];
    const float* Wv = (const float*)d_in[8];
    const float* bv = (const float*)d_in[9];
    const float* Web = (const float*)d_in[10];
    const float* beb = (const float*)d_in[11];
    const float* W1 = (const float*)d_in[12];
    const float* b1 = (const float*)d_in[13];
    const float* W2 = (const float*)d_in[14];
    const float* b2 = (const float*)d_in[15];
    const float* gamma = (const float*)d_in[16];
    const float* beta  = (const float*)d_in[17];
    float* out = (float*)d_out;

    const int N  = in_sizes[0] / HDIM;
    const int E  = in_sizes[2];
    const int ET = in_sizes[3] / HDIM;
    const int* src = edge_idx;
    const int* tgt = edge_idx + E;

    float *pQp, *pbp, *pb1t;
    cudaGetSymbolAddress((void**)&pQp, g_Qp);
    cudaGetSymbolAddress((void**)&pbp, g_bp);
    cudaGetSymbolAddress((void**)&pb1t, g_b1t);
    __nv_bfloat16 *pAhi, *pAlo, *pThi, *pTlo, *pWpH, *pWpL, *pW1H, *pW1L, *pW2H, *pW2L;
    cudaGetSymbolAddress((void**)&pAhi, g_Ahi);
    cudaGetSymbolAddress((void**)&pAlo, g_Alo);
    cudaGetSymbolAddress((void**)&pThi, g_Thi);
    cudaGetSymbolAddress((void**)&pTlo, g_Tlo);
    cudaGetSymbolAddress((void**)&pWpH, g_WpH);
    cudaGetSymbolAddress((void**)&pWpL, g_WpL);
    cudaGetSymbolAddress((void**)&pW1H, g_W1H);
    cudaGetSymbolAddress((void**)&pW1L, g_W1L);
    cudaGetSymbolAddress((void**)&pW2H, g_W2H);
    cudaGetSymbolAddress((void**)&pW2L, g_W2L);

    cudaFuncSetAttribute((const void*)mma_gemm<128, 1>,
                         cudaFuncAttributeMaxDynamicSharedMemorySize, SMEM_BYTES);
    cudaFuncSetAttribute((const void*)mma_gemm<256, 2>,
                         cudaFuncAttributeMaxDynamicSharedMemorySize, SMEM_BYTES);
    cudaFuncSetAttribute((const void*)mma_gemm<128, 3>,
                         cudaFuncAttributeMaxDynamicSharedMemorySize, SMEM_BYTES);

    // 1. zero hagg / exsum
    init_kernel<<<(N * HDIM + 255) / 256, 256>>>(N);

    // 2. EK/EV/ebias -> combined small matrices -> weight bf16 split
    etype_v2<<<ET, 128>>>(edge_emb, Wk, Wv, Web, beb);
    combo_v2<<<268, 128>>>(Wq, bq, Wk, bk, Wv, bv, W1, b1);
    wconvert_kernel<<<(66560 + 255) / 256, 256>>>(W1, W2);

    // 3. Q' GEMM with fused QEK side-output
    int gemm_blocks = (N + BM - 1) / BM;
    mma_gemm<128, 1><<<gemm_blocks, 256, SMEM_BYTES>>>(
        hidden, nullptr, nullptr, pWpH, pWpL, pbp, pQp, nullptr, nullptr, nullptr, N);

    // 4. fused edge pass
    edge_fused_kernel<<<(E + 7) / 8, 256>>>(hidden, src, tgt, etype, E);

    // 5. normalize: wex + AGG bf16 split
    normalize_kernel<<<(N + 7) / 8, 256>>>(N);

    // 6. FFN1 -> T (bf16 hi/lo)
    mma_gemm<256, 2><<<gemm_blocks, 256, SMEM_BYTES>>>(
        hidden, pAhi, pAlo, pW1H, pW1L, pb1t, nullptr, nullptr, nullptr, nullptr, N);

    // 7. FFN2 + residual + layernorm -> out
    mma_gemm<128, 3><<<gemm_blocks, 256, SMEM_BYTES>>>(
        nullptr, pThi, pTlo, pW2H, pW2L, b2, out, hidden, gamma, beta, N);
}

// round 15
// speedup vs baseline: 1.0070x; 1.0070x over previous
#include <cuda_runtime.h>
#include <cuda_bf16.h>
#include <math.h>

// Problem constants (B=1, N=50000, E=600000, H=128, ET=8)
#define NMAX 50000
#define EMAX 600000
#define HDIM 128
#define ETMAX 8

// ---------------- scratch ----------------
__device__ float g_Qp[NMAX * HDIM];     // Q' = scale*q @ Wk^T
__device__ float g_hagg[NMAX * HDIM];   // sum of ex * hidden[src]
__device__ float g_QEK[NMAX * ETMAX];   // scale*q.(EK[ty]+bk) + ebias[ty]
__device__ float g_exsum[NMAX * ETMAX];
__device__ float g_wex[NMAX * ETMAX];
__device__ float g_EK[ETMAX * HDIM];
__device__ float g_EV[ETMAX * HDIM];
__device__ float g_ebias[ETMAX];
__device__ float g_bp[HDIM];
__device__ float g_cbias[ETMAX];
__device__ float g_EVW[ETMAX * HDIM];   // EV @ W1[128:256]
__device__ float g_b1t[HDIM];           // b1 + bv @ W1[128:256]

// pre-split bf16 hi/lo operands (k-loop is conversion-free for these)
__device__ __nv_bfloat16 g_Ahi[NMAX * HDIM], g_Alo[NMAX * HDIM];   // hagg*invsm
__device__ __nv_bfloat16 g_Thi[NMAX * HDIM], g_Tlo[NMAX * HDIM];   // FFN1 out
__device__ __nv_bfloat16 g_WpH[HDIM * HDIM], g_WpL[HDIM * HDIM];
__device__ __nv_bfloat16 g_W1H[2 * HDIM * HDIM], g_W1L[2 * HDIM * HDIM]; // W1top ⊕ WvW1
__device__ __nv_bfloat16 g_W2H[HDIM * HDIM], g_W2L[HDIM * HDIM];
__device__ __nv_bfloat16 g_QEH[HDIM * ETMAX], g_QEL[HDIM * ETMAX];

#define SCALE 0.08838834764831845f  // 1/sqrt(128)

// ---------------- helpers ----------------
__device__ __forceinline__ unsigned pack_bf16(__nv_bfloat16 lo_k, __nv_bfloat16 hi_k) {
    return ((unsigned)__bfloat16_as_ushort(hi_k) << 16) | (unsigned)__bfloat16_as_ushort(lo_k);
}
__device__ __forceinline__ void split_bf16(float v, __nv_bfloat16& hi, __nv_bfloat16& lo) {
    hi = __float2bfloat16(v);
    lo = __float2bfloat16(v - __bfloat162float(hi));
}
__device__ __forceinline__ void mma_bf16(float c[4], const unsigned a[4], const unsigned b[2]) {
    asm volatile(
        "mma.sync.aligned.m16n8k16.row.col.f32.bf16.bf16.f32 "
        "{%0,%1,%2,%3}, {%4,%5,%6,%7}, {%8,%9}, {%0,%1,%2,%3};"
        : "+f"(c[0]), "+f"(c[1]), "+f"(c[2]), "+f"(c[3])
        : "r"(a[0]), "r"(a[1]), "r"(a[2]), "r"(a[3]), "r"(b[0]), "r"(b[1]));
}
__device__ __forceinline__ void ldsm_x4(unsigned r[4], unsigned addr) {
    asm volatile("ldmatrix.sync.aligned.m8n8.x4.shared.b16 {%0,%1,%2,%3}, [%4];"
                 : "=r"(r[0]), "=r"(r[1]), "=r"(r[2]), "=r"(r[3]) : "r"(addr));
}
__device__ __forceinline__ void ldsm_x4_t(unsigned r[4], unsigned addr) {
    asm volatile("ldmatrix.sync.aligned.m8n8.x4.trans.shared.b16 {%0,%1,%2,%3}, [%4];"
                 : "=r"(r[0]), "=r"(r[1]), "=r"(r[2]), "=r"(r[3]) : "r"(addr));
}

// ---------------- init: hagg=0, exsum=0 ----------------
__global__ void init_kernel(int Nn) {
    int i = blockIdx.x * blockDim.x + threadIdx.x;
    if (i < Nn * HDIM) g_hagg[i] = 0.0f;
    if (i < Nn * ETMAX) g_exsum[i] = 0.0f;
}

// ---------------- EK/EV/ebias: block per edge type ----------------
__global__ void etype_v2(const float* __restrict__ edge_emb,
                         const float* __restrict__ Wk,
                         const float* __restrict__ Wv,
                         const float* __restrict__ Web,
                         const float* __restrict__ beb) {
    __shared__ float eh[HDIM];
    int ty = blockIdx.x, j = threadIdx.x;
    eh[j] = edge_emb[ty * HDIM + j];
    __syncthreads();
    float k0 = 0, k1 = 0, k2 = 0, k3 = 0;
    float v0 = 0, v1 = 0, v2 = 0, v3 = 0;
#pragma unroll 8
    for (int k = 0; k < HDIM; k += 4) {
        k0 = fmaf(eh[k],     Wk[(k)     * HDIM + j], k0);
        k1 = fmaf(eh[k + 1], Wk[(k + 1) * HDIM + j], k1);
        k2 = fmaf(eh[k + 2], Wk[(k + 2) * HDIM + j], k2);
        k3 = fmaf(eh[k + 3], Wk[(k + 3) * HDIM + j], k3);
        v0 = fmaf(eh[k],     Wv[(k)     * HDIM + j], v0);
        v1 = fmaf(eh[k + 1], Wv[(k + 1) * HDIM + j], v1);
        v2 = fmaf(eh[k + 2], Wv[(k + 2) * HDIM + j], v2);
        v3 = fmaf(eh[k + 3], Wv[(k + 3) * HDIM + j], v3);
    }
    g_EK[ty * HDIM + j] = (k0 + k1) + (k2 + k3);
    g_EV[ty * HDIM + j] = (v0 + v1) + (v2 + v3);
    if (j == 0) {
        float a0 = 0, a1 = 0, a2 = 0, a3 = 0;
        for (int k = 0; k < HDIM; k += 4) {
            a0 = fmaf(eh[k], Web[k], a0);
            a1 = fmaf(eh[k + 1], Web[k + 1], a1);
            a2 = fmaf(eh[k + 2], Web[k + 2], a2);
            a3 = fmaf(eh[k + 3], Web[k + 3], a3);
        }
        g_ebias[ty] = (a0 + a1) + (a2 + a3) + beb[0];
    }
}

// ---------------- combined precompute v3: fuses all bf16 splits ----------------
// blocks:
//   [0,128)    : WpH/L row m        = split(SCALE * Wq[m,:] @ Wk^T)
//   [128,256)  : W1H/L row (128+m)  = split(Wv[m,:] @ W1b)
//   256        : bp                 (fp32)
//   257        : b1t                (fp32)
//   [258,266)  : EVW row            (fp32)
//   266        : QEH/L              = split(SCALE * Wq @ (EK+bk)^T)
//   267        : cbias              (fp32)
//   [268,396)  : W1H/L row r=b-268  = split(W1[r,:])
//   [396,524)  : W2H/L row r=b-396  = split(W2[r,:])
__global__ void combo_v3(const float* __restrict__ Wq, const float* __restrict__ bq,
                         const float* __restrict__ Wk, const float* __restrict__ bk,
                         const float* __restrict__ Wv, const float* __restrict__ bv,
                         const float* __restrict__ W1, const float* __restrict__ b1,
                         const float* __restrict__ W2) {
    __shared__ float row[HDIM];
    int b = blockIdx.x, t = threadIdx.x;
    const float* W1b = W1 + HDIM * HDIM;  // rows 128..255

    if (b >= 268) {
        // pure weight splits
        float v;
        __nv_bfloat16 *dh, *dl;
        int o;
        if (b < 396) { int r = b - 268; v = W1[r * HDIM + t]; dh = g_W1H; dl = g_W1L; o = r * HDIM + t; }
        else         { int r = b - 396; v = W2[r * HDIM + t]; dh = g_W2H; dl = g_W2L; o = r * HDIM + t; }
        __nv_bfloat16 hi, lo;
        split_bf16(v, hi, lo);
        dh[o] = hi; dl[o] = lo;
        return;
    }

    if (b < 128 || b == 256) {
        row[t] = (b < 128) ? Wq[b * HDIM + t] : bq[t];
        __syncthreads();
        const float4* wr = (const float4*)(Wk + t * HDIM);
        float a0 = 0, a1 = 0, a2 = 0, a3 = 0;
#pragma unroll 8
        for (int j = 0; j < 32; j++) {
            float4 w = wr[j];
            float4 q = *(const float4*)&row[j * 4];
            a0 = fmaf(q.x, w.x, a0);
            a1 = fmaf(q.y, w.y, a1);
            a2 = fmaf(q.z, w.z, a2);
            a3 = fmaf(q.w, w.w, a3);
        }
        float s = ((a0 + a1) + (a2 + a3)) * SCALE;
        if (b < 128) {
            __nv_bfloat16 hi, lo;
            split_bf16(s, hi, lo);
            g_WpH[b * HDIM + t] = hi;
            g_WpL[b * HDIM + t] = lo;
        } else g_bp[t] = s;
    } else if (b < 256 || b == 257 || (b >= 258 && b < 266)) {
        if (b < 256) row[t] = Wv[(b - 128) * HDIM + t];
        else if (b == 257) row[t] = bv[t];
        else row[t] = g_EV[(b - 258) * HDIM + t];
        __syncthreads();
        float a0 = 0, a1 = 0, a2 = 0, a3 = 0;
#pragma unroll 8
        for (int k = 0; k < HDIM; k += 4) {
            a0 = fmaf(row[k],     W1b[(k)     * HDIM + t], a0);
            a1 = fmaf(row[k + 1], W1b[(k + 1) * HDIM + t], a1);
            a2 = fmaf(row[k + 2], W1b[(k + 2) * HDIM + t], a2);
            a3 = fmaf(row[k + 3], W1b[(k + 3) * HDIM + t], a3);
        }
        float s = (a0 + a1) + (a2 + a3);
        if (b < 256) {
            int o = (HDIM + (b - 128)) * HDIM + t;   // bottom half of merged W1
            __nv_bfloat16 hi, lo;
            split_bf16(s, hi, lo);
            g_W1H[o] = hi;
            g_W1L[o] = lo;
        } else if (b == 257) g_b1t[t] = s + b1[t];
        else g_EVW[(b - 258) * HDIM + t] = s;
    } else if (b == 266) {
        row[t] = bk[t];
        __syncthreads();
        float acc[ETMAX] = {};
        const float4* qr = (const float4*)(Wq + t * HDIM);
#pragma unroll 4
        for (int j4 = 0; j4 < 32; j4++) {
            float4 q = qr[j4];
            float4 bb = *(const float4*)&row[j4 * 4];
#pragma unroll
            for (int ty = 0; ty < ETMAX; ty++) {
                float4 ek = *(const float4*)&g_EK[ty * HDIM + j4 * 4];
                acc[ty] += q.x * (ek.x + bb.x) + q.y * (ek.y + bb.y)
                         + q.z * (ek.z + bb.z) + q.w * (ek.w + bb.w);
            }
        }
#pragma unroll
        for (int ty = 0; ty < ETMAX; ty++) {
            __nv_bfloat16 hi, lo;
            split_bf16(acc[ty] * SCALE, hi, lo);
            g_QEH[t * ETMAX + ty] = hi;
            g_QEL[t * ETMAX + ty] = lo;
        }
    } else {
        if (t < ETMAX) {
            float a0 = 0, a1 = 0, a2 = 0, a3 = 0;
            for (int j = 0; j < HDIM; j += 4) {
                a0 = fmaf(bq[j],     g_EK[t * HDIM + j]     + bk[j],     a0);
                a1 = fmaf(bq[j + 1], g_EK[t * HDIM + j + 1] + bk[j + 1], a1);
                a2 = fmaf(bq[j + 2], g_EK[t * HDIM + j + 2] + bk[j + 2], a2);
                a3 = fmaf(bq[j + 3], g_EK[t * HDIM + j + 3] + bk[j + 3], a3);
            }
            g_cbias[t] = ((a0 + a1) + (a2 + a3)) * SCALE + g_ebias[t];
        }
    }
}

// ---------------- bf16x2 tensor-core GEMM, BK=64, ldmatrix, pre-split B ----------------
// MODE 1: Q' GEMM (A=hidden fp32-split) + QEK side-output.
// MODE 2: FFN1 (A k<128: hidden fp32-split; k>=128: pre-split AGG; W=g_W1 256 rows;
//         +wex@EVW, silu) -> writes T as bf16 hi/lo.
// MODE 3: FFN2 (A=T pre-split) + residual + layernorm -> out.
constexpr int BM = 64, BN = 128, BK = 64;
constexpr int LDK = BK + 8;   // 72 bf16 -> 144 B rows
constexpr int LDN = BN + 8;   // 136 bf16 -> 272 B rows

constexpr int OFF_A_HI = 0;                       // bf16 [64][72] = 9216
constexpr int OFF_A_LO = 9216;
constexpr int OFF_B_HI = 18432;                   // bf16 [64][136] = 17408
constexpr int OFF_B_LO = 35840;
constexpr int OFF_QE_HI = 53248;                  // bf16 [64][8] = 1024 (MODE 1)
constexpr int OFF_QE_LO = 54272;
constexpr int OFF_EVW  = 53248;                   // float [8][128] = 4096 (MODE 2)
constexpr int OFF_WEX  = 57344;                   // float [64][8] = 2048 (MODE 2)
constexpr int SMEM_BYTES = 61440;
// MODE 3 epilogue aliases [0, 32768) as float Us[64][128].

template <int KDIM, int MODE>
__global__ void __launch_bounds__(256, 2)
mma_gemm(const float* __restrict__ A,
         const __nv_bfloat16* __restrict__ AH, const __nv_bfloat16* __restrict__ AL,
         const __nv_bfloat16* __restrict__ WH, const __nv_bfloat16* __restrict__ WL,
         const float* __restrict__ bias,
         float* __restrict__ C,
         const float* __restrict__ hidden, const float* __restrict__ gamma,
         const float* __restrict__ beta,
         int M) {
    extern __shared__ char dynsmem[];
    __nv_bfloat16* As_hi = (__nv_bfloat16*)(dynsmem + OFF_A_HI);
    __nv_bfloat16* As_lo = (__nv_bfloat16*)(dynsmem + OFF_A_LO);
    __nv_bfloat16* Bs_hi = (__nv_bfloat16*)(dynsmem + OFF_B_HI);
    __nv_bfloat16* Bs_lo = (__nv_bfloat16*)(dynsmem + OFF_B_LO);
    __nv_bfloat16* QE_hi = (__nv_bfloat16*)(dynsmem + OFF_QE_HI);
    __nv_bfloat16* QE_lo = (__nv_bfloat16*)(dynsmem + OFF_QE_LO);
    float* evws = (float*)(dynsmem + OFF_EVW);
    float* wexs = (float*)(dynsmem + OFF_WEX);
    float* Us   = (float*)dynsmem;

    const int t = threadIdx.x;
    const int block_m = blockIdx.x * BM;
    const int lane = t & 31;
    const int wid = t >> 5;
    const int warp_m = (wid >> 2) * 32;
    const int warp_n = (wid & 3) * 32;
    const int lg = lane >> 2;
    const int lt = lane & 3;

    if (MODE == 2) {
        {
            int ty = t >> 5, n4 = (t & 31) * 4;
            *(float4*)&evws[ty * HDIM + n4] = *(const float4*)(g_EVW + ty * HDIM + n4);
        }
        if (t < 128) {
            int r = t >> 1, half = t & 1;
            int gm = block_m + r;
            float4 v = make_float4(0.f, 0.f, 0.f, 0.f);
            if (gm < M) v = *(const float4*)(g_wex + gm * ETMAX + half * 4);
            *(float4*)&wexs[r * ETMAX + half * 4] = v;
        }
    }

    // ---- ldmatrix per-lane base addresses ----
    unsigned sb = (unsigned)__cvta_generic_to_shared(dynsmem);
    unsigned a_addr0 = sb + OFF_A_HI + (warp_m + (lane & 15)) * (LDK * 2) + ((lane >> 4) * 8) * 2;
    unsigned a_addr1 = a_addr0 + 16 * (LDK * 2);
    unsigned b_row = ((lane & 7) + ((lane >> 3) & 1) * 8);
    unsigned b_addr0 = sb + OFF_B_HI + b_row * (LDN * 2) + (warp_n + (lane >> 4) * 8) * 2;
    unsigned b_addr1 = b_addr0 + 16 * 2;
    constexpr unsigned A_LO_D = OFF_A_LO - OFF_A_HI;
    constexpr unsigned B_LO_D = OFF_B_LO - OFF_B_HI;

    float acc[2][4][4];
#pragma unroll
    for (int mi = 0; mi < 2; mi++)
#pragma unroll
        for (int ni = 0; ni < 4; ni++)
#pragma unroll
            for (int r = 0; r < 4; r++) acc[mi][ni][r] = 0.0f;

    float acc_q[2][4];
    if (MODE == 1) {
#pragma unroll
        for (int mi = 0; mi < 2; mi++)
#pragma unroll
            for (int r = 0; r < 4; r++) acc_q[mi][r] = 0.0f;
    }

    for (int k0 = 0; k0 < KDIM; k0 += BK) {
        // ---- A tile ----
        if (MODE == 3 || (MODE == 2 && k0 >= HDIM)) {
            int colbase = (MODE == 3) ? k0 : (k0 - HDIM);
#pragma unroll
            for (int i = 0; i < 2; i++) {
                int idx = t + i * 256;
                int m = idx >> 3;
                int k8 = (idx & 7) * 8;
                int gm = block_m + m;
                uint4 vh = make_uint4(0, 0, 0, 0), vl = make_uint4(0, 0, 0, 0);
                if (gm < M) {
                    vh = *(const uint4*)(AH + (size_t)gm * HDIM + colbase + k8);
                    vl = *(const uint4*)(AL + (size_t)gm * HDIM + colbase + k8);
                }
                *(uint4*)&As_hi[m * LDK + k8] = vh;
                *(uint4*)&As_lo[m * LDK + k8] = vl;
            }
        } else {
#pragma unroll
            for (int i = 0; i < 4; i++) {
                int idx = t + i * 256;
                int m = idx >> 4;
                int k4 = (idx & 15) * 4;
                int gm = block_m + m;
                float4 v = make_float4(0.f, 0.f, 0.f, 0.f);
                if (gm < M) v = *(const float4*)(A + (size_t)gm * HDIM + k0 + k4);
                __nv_bfloat16 hx, lx, hy, ly, hz, lz, hw, lw;
                split_bf16(v.x, hx, lx); split_bf16(v.y, hy, ly);
                split_bf16(v.z, hz, lz); split_bf16(v.w, hw, lw);
                *(uint2*)&As_hi[m * LDK + k4] = make_uint2(pack_bf16(hx, hy), pack_bf16(hz, hw));
                *(uint2*)&As_lo[m * LDK + k4] = make_uint2(pack_bf16(lx, ly), pack_bf16(lz, lw));
            }
        }
        // ---- B tile: pre-split bf16, pure copy ----
#pragma unroll
        for (int i = 0; i < 4; i++) {
            int idx = t + i * 256;
            int kk = idx >> 4;
            int n8 = (idx & 15) * 8;
            size_t off = (size_t)(k0 + kk) * BN + n8;
            *(uint4*)&Bs_hi[kk * LDN + n8] = *(const uint4*)(WH + off);
            *(uint4*)&Bs_lo[kk * LDN + n8] = *(const uint4*)(WL + off);
        }
        // ---- WqEK tile (MODE 1) ----
        if (MODE == 1 && t < 128) {
            int h = t >> 6;     // 0 = hi, 1 = lo
            int c = t & 63;
            const __nv_bfloat16* s = (h ? g_QEL : g_QEH) + (size_t)(k0 + c) * ETMAX;
            __nv_bfloat16* d = (h ? QE_lo : QE_hi) + c * 8;
            *(uint4*)d = *(const uint4*)s;
        }
        __syncthreads();

#pragma unroll
        for (int ks = 0; ks < BK; ks += 16) {
            unsigned ah[2][4], al[2][4], bh[4][2], bl[4][2];
            ldsm_x4(ah[0], a_addr0 + ks * 2);
            ldsm_x4(ah[1], a_addr1 + ks * 2);
            ldsm_x4(al[0], a_addr0 + A_LO_D + ks * 2);
            ldsm_x4(al[1], a_addr1 + A_LO_D + ks * 2);
            {
                unsigned q[4];
                ldsm_x4_t(q, b_addr0 + ks * (LDN * 2));
                bh[0][0] = q[0]; bh[0][1] = q[1]; bh[1][0] = q[2]; bh[1][1] = q[3];
                ldsm_x4_t(q, b_addr1 + ks * (LDN * 2));
                bh[2][0] = q[0]; bh[2][1] = q[1]; bh[3][0] = q[2]; bh[3][1] = q[3];
                ldsm_x4_t(q, b_addr0 + B_LO_D + ks * (LDN * 2));
                bl[0][0] = q[0]; bl[0][1] = q[1]; bl[1][0] = q[2]; bl[1][1] = q[3];
                ldsm_x4_t(q, b_addr1 + B_LO_D + ks * (LDN * 2));
                bl[2][0] = q[0]; bl[2][1] = q[1]; bl[3][0] = q[2]; bl[3][1] = q[3];
            }
#pragma unroll
            for (int mi = 0; mi < 2; mi++)
#pragma unroll
                for (int ni = 0; ni < 4; ni++) {
                    mma_bf16(acc[mi][ni], ah[mi], bl[ni]);
                    mma_bf16(acc[mi][ni], al[mi], bh[ni]);
                    mma_bf16(acc[mi][ni], ah[mi], bh[ni]);
                }
            if (MODE == 1 && warp_n == 0) {
                unsigned qh[2], ql[2];
                int k = ks + lt * 2;
                qh[0] = pack_bf16(QE_hi[k * 8 + lg], QE_hi[(k + 1) * 8 + lg]);
                qh[1] = pack_bf16(QE_hi[(k + 8) * 8 + lg], QE_hi[(k + 9) * 8 + lg]);
                ql[0] = pack_bf16(QE_lo[k * 8 + lg], QE_lo[(k + 1) * 8 + lg]);
                ql[1] = pack_bf16(QE_lo[(k + 8) * 8 + lg], QE_lo[(k + 9) * 8 + lg]);
#pragma unroll
                for (int mi = 0; mi < 2; mi++) {
                    mma_bf16(acc_q[mi], ah[mi], ql);
                    mma_bf16(acc_q[mi], al[mi], qh);
                    mma_bf16(acc_q[mi], ah[mi], qh);
                }
            }
        }
        __syncthreads();
    }

    // ---- epilogue ----
    if (MODE == 1) {
#pragma unroll
        for (int mi = 0; mi < 2; mi++)
#pragma unroll
            for (int ni = 0; ni < 4; ni++) {
                int n = warp_n + ni * 8 + lt * 2;
                float b0 = bias[n], b1 = bias[n + 1];
#pragma unroll
                for (int h = 0; h < 2; h++) {
                    int gm = block_m + warp_m + mi * 16 + lg + h * 8;
                    if (gm >= M) continue;
                    *(float2*)(C + (size_t)gm * BN + n) =
                        make_float2(acc[mi][ni][2 * h] + b0, acc[mi][ni][2 * h + 1] + b1);
                }
            }
        if (warp_n == 0) {
            float cb0 = g_cbias[lt * 2], cb1 = g_cbias[lt * 2 + 1];
#pragma unroll
            for (int mi = 0; mi < 2; mi++)
#pragma unroll
                for (int h = 0; h < 2; h++) {
                    int gm = block_m + warp_m + mi * 16 + lg + h * 8;
                    if (gm >= M) continue;
                    *(float2*)(g_QEK + gm * ETMAX + lt * 2) =
                        make_float2(acc_q[mi][2 * h] + cb0, acc_q[mi][2 * h + 1] + cb1);
                }
        }
    } else if (MODE == 2) {
#pragma unroll
        for (int mi = 0; mi < 2; mi++)
#pragma unroll
            for (int ni = 0; ni < 4; ni++) {
                int n = warp_n + ni * 8 + lt * 2;
                float b0 = bias[n], b1 = bias[n + 1];
#pragma unroll
                for (int h = 0; h < 2; h++) {
                    int r = warp_m + mi * 16 + lg + h * 8;
                    int gm = block_m + r;
                    if (gm >= M) continue;
                    float v0 = acc[mi][ni][2 * h] + b0;
                    float v1 = acc[mi][ni][2 * h + 1] + b1;
#pragma unroll
                    for (int ty = 0; ty < ETMAX; ty++) {
                        float wv = wexs[r * ETMAX + ty];
                        v0 = fmaf(wv, evws[ty * HDIM + n], v0);
                        v1 = fmaf(wv, evws[ty * HDIM + n + 1], v1);
                    }
                    v0 = v0 / (1.0f + expf(-v0));
                    v1 = v1 / (1.0f + expf(-v1));
                    __nv_bfloat16 h0, l0, h1, l1;
                    split_bf16(v0, h0, l0);
                    split_bf16(v1, h1, l1);
                    *(unsigned*)&g_Thi[(size_t)gm * HDIM + n] = pack_bf16(h0, h1);
                    *(unsigned*)&g_Tlo[(size_t)gm * HDIM + n] = pack_bf16(l0, l1);
                }
            }
    } else {
        // FFN2 + residual + layernorm fused
#pragma unroll
        for (int mi = 0; mi < 2; mi++)
#pragma unroll
            for (int ni = 0; ni < 4; ni++) {
                int n = warp_n + ni * 8 + lt * 2;
                float b0 = bias[n], b1 = bias[n + 1];
#pragma unroll
                for (int h = 0; h < 2; h++) {
                    int r = warp_m + mi * 16 + lg + h * 8;
                    *(float2*)&Us[r * HDIM + n] =
                        make_float2(acc[mi][ni][2 * h] + b0, acc[mi][ni][2 * h + 1] + b1);
                }
            }
        __syncthreads();
        float4 gm4 = ((const float4*)gamma)[lane];
        float4 bt4 = ((const float4*)beta)[lane];
#pragma unroll
        for (int j = 0; j < 8; j++) {
            int r = wid * 8 + j;
            int gm = block_m + r;
            if (gm >= M) continue;
            float4 u = *(const float4*)&Us[r * HDIM + lane * 4];
            float4 hh = *(const float4*)(hidden + (size_t)gm * HDIM + lane * 4);
            float x0 = hh.x + u.x, x1 = hh.y + u.y, x2 = hh.z + u.z, x3 = hh.w + u.w;
            float sum = x0 + x1 + x2 + x3;
#pragma unroll
            for (int o = 16; o; o >>= 1) sum += __shfl_xor_sync(0xffffffffu, sum, o);
            float mu = sum * (1.0f / 128.0f);
            float d0 = x0 - mu, d1 = x1 - mu, d2 = x2 - mu, d3 = x3 - mu;
            float vs = d0 * d0 + d1 * d1 + d2 * d2 + d3 * d3;
#pragma unroll
            for (int o = 16; o; o >>= 1) vs += __shfl_xor_sync(0xffffffffu, vs, o);
            float inv = rsqrtf(vs * (1.0f / 128.0f) + 1e-5f);
            float4 o4;
            o4.x = d0 * inv * gm4.x + bt4.x;
            o4.y = d1 * inv * gm4.y + bt4.y;
            o4.z = d2 * inv * gm4.z + bt4.z;
            o4.w = d3 * inv * gm4.w + bt4.w;
            *(float4*)(C + (size_t)gm * HDIM + lane * 4) = o4;
        }
    }
}

// ---------------- fused edge pass: 2 edges per warp (16 lanes each) ----------------
__global__ void edge_fused_kernel(const float* __restrict__ hidden,
                                  const int* __restrict__ src, const int* __restrict__ tgt,
                                  const int* __restrict__ etype, int E) {
    int warp = blockIdx.x * 8 + (threadIdx.x >> 5);
    int half = (threadIdx.x >> 4) & 1;
    int e = warp * 2 + half;
    bool valid = (e < E);
    if (warp * 2 >= E) return;           // whole warp out of range
    int ec = valid ? e : (E - 1);        // clamp; predicated stores below
    int sl = threadIdx.x & 15;
    int s = src[ec], g = tgt[ec], ty = etype[ec];
    const float4* qr = (const float4*)(g_Qp + (size_t)g * HDIM);
    const float4* hr = (const float4*)(hidden + (size_t)s * HDIM);
    float4 q0 = qr[sl * 2], q1 = qr[sl * 2 + 1];
    float4 h0 = hr[sl * 2], h1 = hr[sl * 2 + 1];
    float d = q0.x * h0.x + q0.y * h0.y + q0.z * h0.z + q0.w * h0.w
            + q1.x * h1.x + q1.y * h1.y + q1.z * h1.z + q1.w * h1.w;
#pragma unroll
    for (int o = 8; o; o >>= 1) d += __shfl_xor_sync(0xffffffffu, d, o);
    float ex = expf(d + g_QEK[g * ETMAX + ty]);
    if (valid) {
        if (sl == 0) atomicAdd(&g_exsum[g * ETMAX + ty], ex);
        float* dst = g_hagg + (size_t)g * HDIM + sl * 8;
        asm volatile("red.global.add.v4.f32 [%0], {%1, %2, %3, %4};"
                     :: "l"(dst), "f"(ex * h0.x), "f"(ex * h0.y), "f"(ex * h0.z), "f"(ex * h0.w)
                     : "memory");
        asm volatile("red.global.add.v4.f32 [%0], {%1, %2, %3, %4};"
                     :: "l"(dst + 4), "f"(ex * h1.x), "f"(ex * h1.y), "f"(ex * h1.z), "f"(ex * h1.w)
                     : "memory");
    }
}

// ---------------- normalize: wex + AGG bf16 split (warp per node) ----------------
__global__ void normalize_kernel(int Nn) {
    int n = blockIdx.x * 8 + (threadIdx.x >> 5);
    if (n >= Nn) return;
    int lane = threadIdx.x & 31;
    float ex = (lane < ETMAX) ? g_exsum[n * ETMAX + lane] : 0.0f;
    float s = ex;
#pragma unroll
    for (int o = 4; o; o >>= 1) s += __shfl_xor_sync(0xffffffffu, s, o);
    s = __shfl_sync(0xffffffffu, s, 0);
    float inv = (s > 0.0f) ? (1.0f / s) : 0.0f;
    if (lane < ETMAX) g_wex[n * ETMAX + lane] = ex * inv;
    float4 v = ((const float4*)(g_hagg + (size_t)n * HDIM))[lane];
    v.x *= inv; v.y *= inv; v.z *= inv; v.w *= inv;
    __nv_bfloat16 hx, lx, hy, ly, hz, lz, hw, lw;
    split_bf16(v.x, hx, lx); split_bf16(v.y, hy, ly);
    split_bf16(v.z, hz, lz); split_bf16(v.w, hw, lw);
    ((uint2*)(g_Ahi + (size_t)n * HDIM))[lane] = make_uint2(pack_bf16(hx, hy), pack_bf16(hz, hw));
    ((uint2*)(g_Alo + (size_t)n * HDIM))[lane] = make_uint2(pack_bf16(lx, ly), pack_bf16(lz, lw));
}

// ---------------- launch ----------------
extern "C" void kernel_launch(void* const* d_in, const int* in_sizes, int n_in,
                              void* d_out, int out_size) {
    const float* hidden   = (const float*)d_in[0];
    const int*   edge_idx = (const int*)d_in[1];
    const int*   etype    = (const int*)d_in[2];
    const float* edge_emb = (const float*)d_in[3];
    const float* Wq = (const float*)d_in[4];
    const float* bq = (const float*)d_in[5];
    const float* Wk = (const float*)d_in[6];
    const float* bk = (const float*)d_in[7];
    const float* Wv = (const float*)d_in[8];
    const float* bv = (const float*)d_in[9];
    const float* Web = (const float*)d_in[10];
    const float* beb = (const float*)d_in[11];
    const float* W1 = (const float*)d_in[12];
    const float* b1 = (const float*)d_in[13];
    const float* W2 = (const float*)d_in[14];
    const float* b2 = (const float*)d_in[15];
    const float* gamma = (const float*)d_in[16];
    const float* beta  = (const float*)d_in[17];
    float* out = (float*)d_out;

    const int N  = in_sizes[0] / HDIM;
    const int E  = in_sizes[2];
    const int ET = in_sizes[3] / HDIM;
    const int* src = edge_idx;
    const int* tgt = edge_idx + E;

    float *pQp, *pbp, *pb1t;
    cudaGetSymbolAddress((void**)&pQp, g_Qp);
    cudaGetSymbolAddress((void**)&pbp, g_bp);
    cudaGetSymbolAddress((void**)&pb1t, g_b1t);
    __nv_bfloat16 *pAhi, *pAlo, *pThi, *pTlo, *pWpH, *pWpL, *pW1H, *pW1L, *pW2H, *pW2L;
    cudaGetSymbolAddress((void**)&pAhi, g_Ahi);
    cudaGetSymbolAddress((void**)&pAlo, g_Alo);
    cudaGetSymbolAddress((void**)&pThi, g_Thi);
    cudaGetSymbolAddress((void**)&pTlo, g_Tlo);
    cudaGetSymbolAddress((void**)&pWpH, g_WpH);
    cudaGetSymbolAddress((void**)&pWpL, g_WpL);
    cudaGetSymbolAddress((void**)&pW1H, g_W1H);
    cudaGetSymbolAddress((void**)&pW1L, g_W1L);
    cudaGetSymbolAddress((void**)&pW2H, g_W2H);
    cudaGetSymbolAddress((void**)&pW2L, g_W2L);

    cudaFuncSetAttribute((const void*)mma_gemm<128, 1>,
                         cudaFuncAttributeMaxDynamicSharedMemorySize, SMEM_BYTES);
    cudaFuncSetAttribute((const void*)mma_gemm<256, 2>,
                         cudaFuncAttributeMaxDynamicSharedMemorySize, SMEM_BYTES);
    cudaFuncSetAttribute((const void*)mma_gemm<128, 3>,
                         cudaFuncAttributeMaxDynamicSharedMemorySize, SMEM_BYTES);

    // 1. zero hagg / exsum
    init_kernel<<<(N * HDIM + 255) / 256, 256>>>(N);

    // 2. EK/EV/ebias -> combined small matrices + all bf16 splits (one kernel)
    etype_v2<<<ET, 128>>>(edge_emb, Wk, Wv, Web, beb);
    combo_v3<<<524, 128>>>(Wq, bq, Wk, bk, Wv, bv, W1, b1, W2);

    // 3. Q' GEMM with fused QEK side-output
    int gemm_blocks = (N + BM - 1) / BM;
    mma_gemm<128, 1><<<gemm_blocks, 256, SMEM_BYTES>>>(
        hidden, nullptr, nullptr, pWpH, pWpL, pbp, pQp, nullptr, nullptr, nullptr, N);

    // 4. fused edge pass (2 edges per warp)
    int edge_blocks = (E + 15) / 16;
    edge_fused_kernel<<<edge_blocks, 256>>>(hidden, src, tgt, etype, E);

    // 5. normalize: wex + AGG bf16 split
    normalize_kernel<<<(N + 7) / 8, 256>>>(N);

    // 6. FFN1 -> T (bf16 hi/lo)
    mma_gemm<256, 2><<<gemm_blocks, 256, SMEM_BYTES>>>(
        hidden, pAhi, pAlo, pW1H, pW1L, pb1t, nullptr, nullptr, nullptr, nullptr, N);

    // 7. FFN2 + residual + layernorm -> out
    mma_gemm<128, 3><<<gemm_blocks, 256, SMEM_BYTES>>>(
        nullptr, pThi, pTlo, pW2H, pW2L, b2, out, hidden, gamma, beta, N);
}

// round 16
// speedup vs baseline: 1.0071x; 1.0001x over previous
#include <cuda_runtime.h>
#include <cuda_bf16.h>
#include <math.h>

// Problem constants (B=1, N=50000, E=600000, H=128, ET=8)
#define NMAX 50000
#define EMAX 600000
#define HDIM 128
#define ETMAX 8

// ---------------- scratch ----------------
__device__ float g_Qp[NMAX * HDIM];     // Q' = scale*q @ Wk^T
__device__ float g_hagg[NMAX * HDIM];   // sum of ex * hidden[src]
__device__ float g_QEK[NMAX * ETMAX];   // scale*q.(EK[ty]+bk) + ebias[ty]
__device__ float g_exsum[NMAX * ETMAX];
__device__ float g_wex[NMAX * ETMAX];
__device__ float g_EK[ETMAX * HDIM];
__device__ float g_EV[ETMAX * HDIM];
__device__ float g_ebias[ETMAX];
__device__ float g_bp[HDIM];
__device__ float g_cbias[ETMAX];
__device__ float g_EVW[ETMAX * HDIM];   // EV @ W1[128:256]
__device__ float g_b1t[HDIM];           // b1 + bv @ W1[128:256]

// pre-split bf16 hi/lo operands (k-loop is conversion-free for these)
__device__ __nv_bfloat16 g_Ahi[NMAX * HDIM], g_Alo[NMAX * HDIM];   // hagg*invsm
__device__ __nv_bfloat16 g_Thi[NMAX * HDIM], g_Tlo[NMAX * HDIM];   // FFN1 out
__device__ __nv_bfloat16 g_WpH[HDIM * HDIM], g_WpL[HDIM * HDIM];
__device__ __nv_bfloat16 g_W1H[2 * HDIM * HDIM], g_W1L[2 * HDIM * HDIM]; // W1top ⊕ WvW1
__device__ __nv_bfloat16 g_W2H[HDIM * HDIM], g_W2L[HDIM * HDIM];
__device__ __nv_bfloat16 g_QEH[HDIM * ETMAX], g_QEL[HDIM * ETMAX];

#define SCALE 0.08838834764831845f  // 1/sqrt(128)

// ---------------- helpers ----------------
__device__ __forceinline__ unsigned pack_bf16(__nv_bfloat16 lo_k, __nv_bfloat16 hi_k) {
    return ((unsigned)__bfloat16_as_ushort(hi_k) << 16) | (unsigned)__bfloat16_as_ushort(lo_k);
}
__device__ __forceinline__ void split_bf16(float v, __nv_bfloat16& hi, __nv_bfloat16& lo) {
    hi = __float2bfloat16(v);
    lo = __float2bfloat16(v - __bfloat162float(hi));
}
__device__ __forceinline__ void mma_bf16(float c[4], const unsigned a[4], const unsigned b[2]) {
    asm volatile(
        "mma.sync.aligned.m16n8k16.row.col.f32.bf16.bf16.f32 "
        "{%0,%1,%2,%3}, {%4,%5,%6,%7}, {%8,%9}, {%0,%1,%2,%3};"
        : "+f"(c[0]), "+f"(c[1]), "+f"(c[2]), "+f"(c[3])
        : "r"(a[0]), "r"(a[1]), "r"(a[2]), "r"(a[3]), "r"(b[0]), "r"(b[1]));
}
__device__ __forceinline__ void ldsm_x4(unsigned r[4], unsigned addr) {
    asm volatile("ldmatrix.sync.aligned.m8n8.x4.shared.b16 {%0,%1,%2,%3}, [%4];"
                 : "=r"(r[0]), "=r"(r[1]), "=r"(r[2]), "=r"(r[3]) : "r"(addr));
}
__device__ __forceinline__ void ldsm_x4_t(unsigned r[4], unsigned addr) {
    asm volatile("ldmatrix.sync.aligned.m8n8.x4.trans.shared.b16 {%0,%1,%2,%3}, [%4];"
                 : "=r"(r[0]), "=r"(r[1]), "=r"(r[2]), "=r"(r[3]) : "r"(addr));
}

// ---------------- init: hagg=0, exsum=0 ----------------
__global__ void init_kernel(int Nn) {
    int i = blockIdx.x * blockDim.x + threadIdx.x;
    if (i < Nn * HDIM) g_hagg[i] = 0.0f;
    if (i < Nn * ETMAX) g_exsum[i] = 0.0f;
}

// ---------------- EK/EV/ebias: block per edge type ----------------
__global__ void etype_v2(const float* __restrict__ edge_emb,
                         const float* __restrict__ Wk,
                         const float* __restrict__ Wv,
                         const float* __restrict__ Web,
                         const float* __restrict__ beb) {
    __shared__ float eh[HDIM];
    int ty = blockIdx.x, j = threadIdx.x;
    eh[j] = edge_emb[ty * HDIM + j];
    __syncthreads();
    float k0 = 0, k1 = 0, k2 = 0, k3 = 0;
    float v0 = 0, v1 = 0, v2 = 0, v3 = 0;
#pragma unroll 8
    for (int k = 0; k < HDIM; k += 4) {
        k0 = fmaf(eh[k],     Wk[(k)     * HDIM + j], k0);
        k1 = fmaf(eh[k + 1], Wk[(k + 1) * HDIM + j], k1);
        k2 = fmaf(eh[k + 2], Wk[(k + 2) * HDIM + j], k2);
        k3 = fmaf(eh[k + 3], Wk[(k + 3) * HDIM + j], k3);
        v0 = fmaf(eh[k],     Wv[(k)     * HDIM + j], v0);
        v1 = fmaf(eh[k + 1], Wv[(k + 1) * HDIM + j], v1);
        v2 = fmaf(eh[k + 2], Wv[(k + 2) * HDIM + j], v2);
        v3 = fmaf(eh[k + 3], Wv[(k + 3) * HDIM + j], v3);
    }
    g_EK[ty * HDIM + j] = (k0 + k1) + (k2 + k3);
    g_EV[ty * HDIM + j] = (v0 + v1) + (v2 + v3);
    if (j == 0) {
        float a0 = 0, a1 = 0, a2 = 0, a3 = 0;
        for (int k = 0; k < HDIM; k += 4) {
            a0 = fmaf(eh[k], Web[k], a0);
            a1 = fmaf(eh[k + 1], Web[k + 1], a1);
            a2 = fmaf(eh[k + 2], Web[k + 2], a2);
            a3 = fmaf(eh[k + 3], Web[k + 3], a3);
        }
        g_ebias[ty] = (a0 + a1) + (a2 + a3) + beb[0];
    }
}

// ---------------- combined precompute v3: fuses all bf16 splits ----------------
// blocks:
//   [0,128)    : WpH/L row m        = split(SCALE * Wq[m,:] @ Wk^T)
//   [128,256)  : W1H/L row (128+m)  = split(Wv[m,:] @ W1b)
//   256        : bp                 (fp32)
//   257        : b1t                (fp32)
//   [258,266)  : EVW row            (fp32)
//   266        : QEH/L              = split(SCALE * Wq @ (EK+bk)^T)
//   267        : cbias              (fp32)
//   [268,396)  : W1H/L row r=b-268  = split(W1[r,:])
//   [396,524)  : W2H/L row r=b-396  = split(W2[r,:])
__global__ void combo_v3(const float* __restrict__ Wq, const float* __restrict__ bq,
                         const float* __restrict__ Wk, const float* __restrict__ bk,
                         const float* __restrict__ Wv, const float* __restrict__ bv,
                         const float* __restrict__ W1, const float* __restrict__ b1,
                         const float* __restrict__ W2) {
    __shared__ float row[HDIM];
    int b = blockIdx.x, t = threadIdx.x;
    const float* W1b = W1 + HDIM * HDIM;  // rows 128..255

    if (b >= 268) {
        // pure weight splits
        float v;
        __nv_bfloat16 *dh, *dl;
        int o;
        if (b < 396) { int r = b - 268; v = W1[r * HDIM + t]; dh = g_W1H; dl = g_W1L; o = r * HDIM + t; }
        else         { int r = b - 396; v = W2[r * HDIM + t]; dh = g_W2H; dl = g_W2L; o = r * HDIM + t; }
        __nv_bfloat16 hi, lo;
        split_bf16(v, hi, lo);
        dh[o] = hi; dl[o] = lo;
        return;
    }

    if (b < 128 || b == 256) {
        row[t] = (b < 128) ? Wq[b * HDIM + t] : bq[t];
        __syncthreads();
        const float4* wr = (const float4*)(Wk + t * HDIM);
        float a0 = 0, a1 = 0, a2 = 0, a3 = 0;
#pragma unroll 8
        for (int j = 0; j < 32; j++) {
            float4 w = wr[j];
            float4 q = *(const float4*)&row[j * 4];
            a0 = fmaf(q.x, w.x, a0);
            a1 = fmaf(q.y, w.y, a1);
            a2 = fmaf(q.z, w.z, a2);
            a3 = fmaf(q.w, w.w, a3);
        }
        float s = ((a0 + a1) + (a2 + a3)) * SCALE;
        if (b < 128) {
            __nv_bfloat16 hi, lo;
            split_bf16(s, hi, lo);
            g_WpH[b * HDIM + t] = hi;
            g_WpL[b * HDIM + t] = lo;
        } else g_bp[t] = s;
    } else if (b < 256 || b == 257 || (b >= 258 && b < 266)) {
        if (b < 256) row[t] = Wv[(b - 128) * HDIM + t];
        else if (b == 257) row[t] = bv[t];
        else row[t] = g_EV[(b - 258) * HDIM + t];
        __syncthreads();
        float a0 = 0, a1 = 0, a2 = 0, a3 = 0;
#pragma unroll 8
        for (int k = 0; k < HDIM; k += 4) {
            a0 = fmaf(row[k],     W1b[(k)     * HDIM + t], a0);
            a1 = fmaf(row[k + 1], W1b[(k + 1) * HDIM + t], a1);
            a2 = fmaf(row[k + 2], W1b[(k + 2) * HDIM + t], a2);
            a3 = fmaf(row[k + 3], W1b[(k + 3) * HDIM + t], a3);
        }
        float s = (a0 + a1) + (a2 + a3);
        if (b < 256) {
            int o = (HDIM + (b - 128)) * HDIM + t;   // bottom half of merged W1
            __nv_bfloat16 hi, lo;
            split_bf16(s, hi, lo);
            g_W1H[o] = hi;
            g_W1L[o] = lo;
        } else if (b == 257) g_b1t[t] = s + b1[t];
        else g_EVW[(b - 258) * HDIM + t] = s;
    } else if (b == 266) {
        row[t] = bk[t];
        __syncthreads();
        float acc[ETMAX] = {};
        const float4* qr = (const float4*)(Wq + t * HDIM);
#pragma unroll 4
        for (int j4 = 0; j4 < 32; j4++) {
            float4 q = qr[j4];
            float4 bb = *(const float4*)&row[j4 * 4];
#pragma unroll
            for (int ty = 0; ty < ETMAX; ty++) {
                float4 ek = *(const float4*)&g_EK[ty * HDIM + j4 * 4];
                acc[ty] += q.x * (ek.x + bb.x) + q.y * (ek.y + bb.y)
                         + q.z * (ek.z + bb.z) + q.w * (ek.w + bb.w);
            }
        }
#pragma unroll
        for (int ty = 0; ty < ETMAX; ty++) {
            __nv_bfloat16 hi, lo;
            split_bf16(acc[ty] * SCALE, hi, lo);
            g_QEH[t * ETMAX + ty] = hi;
            g_QEL[t * ETMAX + ty] = lo;
        }
    } else {
        if (t < ETMAX) {
            float a0 = 0, a1 = 0, a2 = 0, a3 = 0;
            for (int j = 0; j < HDIM; j += 4) {
                a0 = fmaf(bq[j],     g_EK[t * HDIM + j]     + bk[j],     a0);
                a1 = fmaf(bq[j + 1], g_EK[t * HDIM + j + 1] + bk[j + 1], a1);
                a2 = fmaf(bq[j + 2], g_EK[t * HDIM + j + 2] + bk[j + 2], a2);
                a3 = fmaf(bq[j + 3], g_EK[t * HDIM + j + 3] + bk[j + 3], a3);
            }
            g_cbias[t] = ((a0 + a1) + (a2 + a3)) * SCALE + g_ebias[t];
        }
    }
}

// ---------------- bf16x2 tensor-core GEMM, BK=64, ldmatrix, pre-split B ----------------
// MODE 1: Q' GEMM (A=hidden fp32-split) + QEK side-output.
// MODE 2: FFN1 (A k<128: hidden fp32-split; k>=128: pre-split AGG; W=g_W1 256 rows;
//         +wex@EVW, silu) -> writes T as bf16 hi/lo.
// MODE 3: FFN2 (A=T pre-split) + residual + layernorm -> out.
constexpr int BM = 64, BN = 128, BK = 64;
constexpr int LDK = BK + 8;   // 72 bf16 -> 144 B rows
constexpr int LDN = BN + 8;   // 136 bf16 -> 272 B rows

constexpr int OFF_A_HI = 0;                       // bf16 [64][72] = 9216
constexpr int OFF_A_LO = 9216;
constexpr int OFF_B_HI = 18432;                   // bf16 [64][136] = 17408
constexpr int OFF_B_LO = 35840;
constexpr int OFF_QE_HI = 53248;                  // bf16 [64][8] = 1024 (MODE 1)
constexpr int OFF_QE_LO = 54272;
constexpr int OFF_EVW  = 53248;                   // float [8][128] = 4096 (MODE 2)
constexpr int OFF_WEX  = 57344;                   // float [64][8] = 2048 (MODE 2)
constexpr int SMEM_BYTES = 61440;
// MODE 3 epilogue aliases [0, 32768) as float Us[64][128].

template <int KDIM, int MODE>
__global__ void __launch_bounds__(256, 2)
mma_gemm(const float* __restrict__ A,
         const __nv_bfloat16* __restrict__ AH, const __nv_bfloat16* __restrict__ AL,
         const __nv_bfloat16* __restrict__ WH, const __nv_bfloat16* __restrict__ WL,
         const float* __restrict__ bias,
         float* __restrict__ C,
         const float* __restrict__ hidden, const float* __restrict__ gamma,
         const float* __restrict__ beta,
         int M) {
    extern __shared__ char dynsmem[];
    __nv_bfloat16* As_hi = (__nv_bfloat16*)(dynsmem + OFF_A_HI);
    __nv_bfloat16* As_lo = (__nv_bfloat16*)(dynsmem + OFF_A_LO);
    __nv_bfloat16* Bs_hi = (__nv_bfloat16*)(dynsmem + OFF_B_HI);
    __nv_bfloat16* Bs_lo = (__nv_bfloat16*)(dynsmem + OFF_B_LO);
    __nv_bfloat16* QE_hi = (__nv_bfloat16*)(dynsmem + OFF_QE_HI);
    __nv_bfloat16* QE_lo = (__nv_bfloat16*)(dynsmem + OFF_QE_LO);
    float* evws = (float*)(dynsmem + OFF_EVW);
    float* wexs = (float*)(dynsmem + OFF_WEX);
    float* Us   = (float*)dynsmem;

    const int t = threadIdx.x;
    const int block_m = blockIdx.x * BM;
    const int lane = t & 31;
    const int wid = t >> 5;
    const int warp_m = (wid >> 2) * 32;
    const int warp_n = (wid & 3) * 32;
    const int lg = lane >> 2;
    const int lt = lane & 3;

    if (MODE == 2) {
        {
            int ty = t >> 5, n4 = (t & 31) * 4;
            *(float4*)&evws[ty * HDIM + n4] = *(const float4*)(g_EVW + ty * HDIM + n4);
        }
        if (t < 128) {
            int r = t >> 1, half = t & 1;
            int gm = block_m + r;
            float4 v = make_float4(0.f, 0.f, 0.f, 0.f);
            if (gm < M) v = *(const float4*)(g_wex + gm * ETMAX + half * 4);
            *(float4*)&wexs[r * ETMAX + half * 4] = v;
        }
    }

    // ---- ldmatrix per-lane base addresses ----
    unsigned sb = (unsigned)__cvta_generic_to_shared(dynsmem);
    unsigned a_addr0 = sb + OFF_A_HI + (warp_m + (lane & 15)) * (LDK * 2) + ((lane >> 4) * 8) * 2;
    unsigned a_addr1 = a_addr0 + 16 * (LDK * 2);
    unsigned b_row = ((lane & 7) + ((lane >> 3) & 1) * 8);
    unsigned b_addr0 = sb + OFF_B_HI + b_row * (LDN * 2) + (warp_n + (lane >> 4) * 8) * 2;
    unsigned b_addr1 = b_addr0 + 16 * 2;
    constexpr unsigned A_LO_D = OFF_A_LO - OFF_A_HI;
    constexpr unsigned B_LO_D = OFF_B_LO - OFF_B_HI;

    float acc[2][4][4];
#pragma unroll
    for (int mi = 0; mi < 2; mi++)
#pragma unroll
        for (int ni = 0; ni < 4; ni++)
#pragma unroll
            for (int r = 0; r < 4; r++) acc[mi][ni][r] = 0.0f;

    float acc_q[2][4];
    if (MODE == 1) {
#pragma unroll
        for (int mi = 0; mi < 2; mi++)
#pragma unroll
            for (int r = 0; r < 4; r++) acc_q[mi][r] = 0.0f;
    }

    for (int k0 = 0; k0 < KDIM; k0 += BK) {
        // ---- A tile ----
        if (MODE == 3 || (MODE == 2 && k0 >= HDIM)) {
            int colbase = (MODE == 3) ? k0 : (k0 - HDIM);
#pragma unroll
            for (int i = 0; i < 2; i++) {
                int idx = t + i * 256;
                int m = idx >> 3;
                int k8 = (idx & 7) * 8;
                int gm = block_m + m;
                uint4 vh = make_uint4(0, 0, 0, 0), vl = make_uint4(0, 0, 0, 0);
                if (gm < M) {
                    vh = *(const uint4*)(AH + (size_t)gm * HDIM + colbase + k8);
                    vl = *(const uint4*)(AL + (size_t)gm * HDIM + colbase + k8);
                }
                *(uint4*)&As_hi[m * LDK + k8] = vh;
                *(uint4*)&As_lo[m * LDK + k8] = vl;
            }
        } else {
#pragma unroll
            for (int i = 0; i < 4; i++) {
                int idx = t + i * 256;
                int m = idx >> 4;
                int k4 = (idx & 15) * 4;
                int gm = block_m + m;
                float4 v = make_float4(0.f, 0.f, 0.f, 0.f);
                if (gm < M) v = *(const float4*)(A + (size_t)gm * HDIM + k0 + k4);
                __nv_bfloat16 hx, lx, hy, ly, hz, lz, hw, lw;
                split_bf16(v.x, hx, lx); split_bf16(v.y, hy, ly);
                split_bf16(v.z, hz, lz); split_bf16(v.w, hw, lw);
                *(uint2*)&As_hi[m * LDK + k4] = make_uint2(pack_bf16(hx, hy), pack_bf16(hz, hw));
                *(uint2*)&As_lo[m * LDK + k4] = make_uint2(pack_bf16(lx, ly), pack_bf16(lz, lw));
            }
        }
        // ---- B tile: pre-split bf16, pure copy ----
#pragma unroll
        for (int i = 0; i < 4; i++) {
            int idx = t + i * 256;
            int kk = idx >> 4;
            int n8 = (idx & 15) * 8;
            size_t off = (size_t)(k0 + kk) * BN + n8;
            *(uint4*)&Bs_hi[kk * LDN + n8] = *(const uint4*)(WH + off);
            *(uint4*)&Bs_lo[kk * LDN + n8] = *(const uint4*)(WL + off);
        }
        // ---- WqEK tile (MODE 1) ----
        if (MODE == 1 && t < 128) {
            int h = t >> 6;     // 0 = hi, 1 = lo
            int c = t & 63;
            const __nv_bfloat16* s = (h ? g_QEL : g_QEH) + (size_t)(k0 + c) * ETMAX;
            __nv_bfloat16* d = (h ? QE_lo : QE_hi) + c * 8;
            *(uint4*)d = *(const uint4*)s;
        }
        __syncthreads();

#pragma unroll
        for (int ks = 0; ks < BK; ks += 16) {
            unsigned ah[2][4], al[2][4], bh[4][2], bl[4][2];
            ldsm_x4(ah[0], a_addr0 + ks * 2);
            ldsm_x4(ah[1], a_addr1 + ks * 2);
            ldsm_x4(al[0], a_addr0 + A_LO_D + ks * 2);
            ldsm_x4(al[1], a_addr1 + A_LO_D + ks * 2);
            {
                unsigned q[4];
                ldsm_x4_t(q, b_addr0 + ks * (LDN * 2));
                bh[0][0] = q[0]; bh[0][1] = q[1]; bh[1][0] = q[2]; bh[1][1] = q[3];
                ldsm_x4_t(q, b_addr1 + ks * (LDN * 2));
                bh[2][0] = q[0]; bh[2][1] = q[1]; bh[3][0] = q[2]; bh[3][1] = q[3];
                ldsm_x4_t(q, b_addr0 + B_LO_D + ks * (LDN * 2));
                bl[0][0] = q[0]; bl[0][1] = q[1]; bl[1][0] = q[2]; bl[1][1] = q[3];
                ldsm_x4_t(q, b_addr1 + B_LO_D + ks * (LDN * 2));
                bl[2][0] = q[0]; bl[2][1] = q[1]; bl[3][0] = q[2]; bl[3][1] = q[3];
            }
#pragma unroll
            for (int mi = 0; mi < 2; mi++)
#pragma unroll
                for (int ni = 0; ni < 4; ni++) {
                    mma_bf16(acc[mi][ni], ah[mi], bl[ni]);
                    mma_bf16(acc[mi][ni], al[mi], bh[ni]);
                    mma_bf16(acc[mi][ni], ah[mi], bh[ni]);
                }
            if (MODE == 1 && warp_n == 0) {
                unsigned qh[2], ql[2];
                int k = ks + lt * 2;
                qh[0] = pack_bf16(QE_hi[k * 8 + lg], QE_hi[(k + 1) * 8 + lg]);
                qh[1] = pack_bf16(QE_hi[(k + 8) * 8 + lg], QE_hi[(k + 9) * 8 + lg]);
                ql[0] = pack_bf16(QE_lo[k * 8 + lg], QE_lo[(k + 1) * 8 + lg]);
                ql[1] = pack_bf16(QE_lo[(k + 8) * 8 + lg], QE_lo[(k + 9) * 8 + lg]);
#pragma unroll
                for (int mi = 0; mi < 2; mi++) {
                    mma_bf16(acc_q[mi], ah[mi], ql);
                    mma_bf16(acc_q[mi], al[mi], qh);
                    mma_bf16(acc_q[mi], ah[mi], qh);
                }
            }
        }
        __syncthreads();
    }

    // ---- epilogue ----
    if (MODE == 1) {
#pragma unroll
        for (int mi = 0; mi < 2; mi++)
#pragma unroll
            for (int ni = 0; ni < 4; ni++) {
                int n = warp_n + ni * 8 + lt * 2;
                float b0 = bias[n], b1 = bias[n + 1];
#pragma unroll
                for (int h = 0; h < 2; h++) {
                    int gm = block_m + warp_m + mi * 16 + lg + h * 8;
                    if (gm >= M) continue;
                    *(float2*)(C + (size_t)gm * BN + n) =
                        make_float2(acc[mi][ni][2 * h] + b0, acc[mi][ni][2 * h + 1] + b1);
                }
            }
        if (warp_n == 0) {
            float cb0 = g_cbias[lt * 2], cb1 = g_cbias[lt * 2 + 1];
#pragma unroll
            for (int mi = 0; mi < 2; mi++)
#pragma unroll
                for (int h = 0; h < 2; h++) {
                    int gm = block_m + warp_m + mi * 16 + lg + h * 8;
                    if (gm >= M) continue;
                    *(float2*)(g_QEK + gm * ETMAX + lt * 2) =
                        make_float2(acc_q[mi][2 * h] + cb0, acc_q[mi][2 * h + 1] + cb1);
                }
        }
    } else if (MODE == 2) {
#pragma unroll
        for (int mi = 0; mi < 2; mi++)
#pragma unroll
            for (int ni = 0; ni < 4; ni++) {
                int n = warp_n + ni * 8 + lt * 2;
                float b0 = bias[n], b1 = bias[n + 1];
#pragma unroll
                for (int h = 0; h < 2; h++) {
                    int r = warp_m + mi * 16 + lg + h * 8;
                    int gm = block_m + r;
                    if (gm >= M) continue;
                    float v0 = acc[mi][ni][2 * h] + b0;
                    float v1 = acc[mi][ni][2 * h + 1] + b1;
#pragma unroll
                    for (int ty = 0; ty < ETMAX; ty++) {
                        float wv = wexs[r * ETMAX + ty];
                        v0 = fmaf(wv, evws[ty * HDIM + n], v0);
                        v1 = fmaf(wv, evws[ty * HDIM + n + 1], v1);
                    }
                    v0 = v0 / (1.0f + expf(-v0));
                    v1 = v1 / (1.0f + expf(-v1));
                    __nv_bfloat16 h0, l0, h1, l1;
                    split_bf16(v0, h0, l0);
                    split_bf16(v1, h1, l1);
                    *(unsigned*)&g_Thi[(size_t)gm * HDIM + n] = pack_bf16(h0, h1);
                    *(unsigned*)&g_Tlo[(size_t)gm * HDIM + n] = pack_bf16(l0, l1);
                }
            }
    } else {
        // FFN2 + residual + layernorm fused
#pragma unroll
        for (int mi = 0; mi < 2; mi++)
#pragma unroll
            for (int ni = 0; ni < 4; ni++) {
                int n = warp_n + ni * 8 + lt * 2;
                float b0 = bias[n], b1 = bias[n + 1];
#pragma unroll
                for (int h = 0; h < 2; h++) {
                    int r = warp_m + mi * 16 + lg + h * 8;
                    *(float2*)&Us[r * HDIM + n] =
                        make_float2(acc[mi][ni][2 * h] + b0, acc[mi][ni][2 * h + 1] + b1);
                }
            }
        __syncthreads();
        float4 gm4 = ((const float4*)gamma)[lane];
        float4 bt4 = ((const float4*)beta)[lane];
#pragma unroll
        for (int j = 0; j < 8; j++) {
            int r = wid * 8 + j;
            int gm = block_m + r;
            if (gm >= M) continue;
            float4 u = *(const float4*)&Us[r * HDIM + lane * 4];
            float4 hh = *(const float4*)(hidden + (size_t)gm * HDIM + lane * 4);
            float x0 = hh.x + u.x, x1 = hh.y + u.y, x2 = hh.z + u.z, x3 = hh.w + u.w;
            float sum = x0 + x1 + x2 + x3;
#pragma unroll
            for (int o = 16; o; o >>= 1) sum += __shfl_xor_sync(0xffffffffu, sum, o);
            float mu = sum * (1.0f / 128.0f);
            float d0 = x0 - mu, d1 = x1 - mu, d2 = x2 - mu, d3 = x3 - mu;
            float vs = d0 * d0 + d1 * d1 + d2 * d2 + d3 * d3;
#pragma unroll
            for (int o = 16; o; o >>= 1) vs += __shfl_xor_sync(0xffffffffu, vs, o);
            float inv = rsqrtf(vs * (1.0f / 128.0f) + 1e-5f);
            float4 o4;
            o4.x = d0 * inv * gm4.x + bt4.x;
            o4.y = d1 * inv * gm4.y + bt4.y;
            o4.z = d2 * inv * gm4.z + bt4.z;
            o4.w = d3 * inv * gm4.w + bt4.w;
            *(float4*)(C + (size_t)gm * HDIM + lane * 4) = o4;
        }
    }
}

// ---------------- fused edge pass: 2 edges per warp (16 lanes each) ----------------
__global__ void edge_fused_kernel(const float* __restrict__ hidden,
                                  const int* __restrict__ src, const int* __restrict__ tgt,
                                  const int* __restrict__ etype, int E) {
    int warp = blockIdx.x * 8 + (threadIdx.x >> 5);
    int half = (threadIdx.x >> 4) & 1;
    int e = warp * 2 + half;
    bool valid = (e < E);
    if (warp * 2 >= E) return;           // whole warp out of range
    int ec = valid ? e : (E - 1);        // clamp; predicated stores below
    int sl = threadIdx.x & 15;
    int s = src[ec], g = tgt[ec], ty = etype[ec];
    const float4* qr = (const float4*)(g_Qp + (size_t)g * HDIM);
    const float4* hr = (const float4*)(hidden + (size_t)s * HDIM);
    float4 q0 = qr[sl * 2], q1 = qr[sl * 2 + 1];
    float4 h0 = hr[sl * 2], h1 = hr[sl * 2 + 1];
    float d = q0.x * h0.x + q0.y * h0.y + q0.z * h0.z + q0.w * h0.w
            + q1.x * h1.x + q1.y * h1.y + q1.z * h1.z + q1.w * h1.w;
#pragma unroll
    for (int o = 8; o; o >>= 1) d += __shfl_xor_sync(0xffffffffu, d, o);
    float ex = expf(d + g_QEK[g * ETMAX + ty]);
    if (valid) {
        if (sl == 0) atomicAdd(&g_exsum[g * ETMAX + ty], ex);
        float* dst = g_hagg + (size_t)g * HDIM + sl * 8;
        asm volatile("red.global.add.v4.f32 [%0], {%1, %2, %3, %4};"
                     :: "l"(dst), "f"(ex * h0.x), "f"(ex * h0.y), "f"(ex * h0.z), "f"(ex * h0.w)
                     : "memory");
        asm volatile("red.global.add.v4.f32 [%0], {%1, %2, %3, %4};"
                     :: "l"(dst + 4), "f"(ex * h1.x), "f"(ex * h1.y), "f"(ex * h1.z), "f"(ex * h1.w)
                     : "memory");
    }
}

// ---------------- normalize: wex + AGG bf16 split (warp per node) ----------------
__global__ void normalize_kernel(int Nn) {
    int n = blockIdx.x * 8 + (threadIdx.x >> 5);
    if (n >= Nn) return;
    int lane = threadIdx.x & 31;
    float ex = (lane < ETMAX) ? g_exsum[n * ETMAX + lane] : 0.0f;
    float s = ex;
#pragma unroll
    for (int o = 4; o; o >>= 1) s += __shfl_xor_sync(0xffffffffu, s, o);
    s = __shfl_sync(0xffffffffu, s, 0);
    float inv = (s > 0.0f) ? (1.0f / s) : 0.0f;
    if (lane < ETMAX) g_wex[n * ETMAX + lane] = ex * inv;
    float4 v = ((const float4*)(g_hagg + (size_t)n * HDIM))[lane];
    v.x *= inv; v.y *= inv; v.z *= inv; v.w *= inv;
    __nv_bfloat16 hx, lx, hy, ly, hz, lz, hw, lw;
    split_bf16(v.x, hx, lx); split_bf16(v.y, hy, ly);
    split_bf16(v.z, hz, lz); split_bf16(v.w, hw, lw);
    ((uint2*)(g_Ahi + (size_t)n * HDIM))[lane] = make_uint2(pack_bf16(hx, hy), pack_bf16(hz, hw));
    ((uint2*)(g_Alo + (size_t)n * HDIM))[lane] = make_uint2(pack_bf16(lx, ly), pack_bf16(lz, lw));
}

// ---------------- launch ----------------
extern "C" void kernel_launch(void* const* d_in, const int* in_sizes, int n_in,
                              void* d_out, int out_size) {
    const float* hidden   = (const float*)d_in[0];
    const int*   edge_idx = (const int*)d_in[1];
    const int*   etype    = (const int*)d_in[2];
    const float* edge_emb = (const float*)d_in[3];
    const float* Wq = (const float*)d_in[4];
    const float* bq = (const float*)d_in[5];
    const float* Wk = (const float*)d_in[6];
    const float* bk = (const float*)d_in[7];
    const float* Wv = (const float*)d_in[8];
    const float* bv = (const float*)d_in[9];
    const float* Web = (const float*)d_in[10];
    const float* beb = (const float*)d_in[11];
    const float* W1 = (const float*)d_in[12];
    const float* b1 = (const float*)d_in[13];
    const float* W2 = (const float*)d_in[14];
    const float* b2 = (const float*)d_in[15];
    const float* gamma = (const float*)d_in[16];
    const float* beta  = (const float*)d_in[17];
    float* out = (float*)d_out;

    const int N  = in_sizes[0] / HDIM;
    const int E  = in_sizes[2];
    const int ET = in_sizes[3] / HDIM;
    const int* src = edge_idx;
    const int* tgt = edge_idx + E;

    float *pQp, *pbp, *pb1t;
    cudaGetSymbolAddress((void**)&pQp, g_Qp);
    cudaGetSymbolAddress((void**)&pbp, g_bp);
    cudaGetSymbolAddress((void**)&pb1t, g_b1t);
    __nv_bfloat16 *pAhi, *pAlo, *pThi, *pTlo, *pWpH, *pWpL, *pW1H, *pW1L, *pW2H, *pW2L;
    cudaGetSymbolAddress((void**)&pAhi, g_Ahi);
    cudaGetSymbolAddress((void**)&pAlo, g_Alo);
    cudaGetSymbolAddress((void**)&pThi, g_Thi);
    cudaGetSymbolAddress((void**)&pTlo, g_Tlo);
    cudaGetSymbolAddress((void**)&pWpH, g_WpH);
    cudaGetSymbolAddress((void**)&pWpL, g_WpL);
    cudaGetSymbolAddress((void**)&pW1H, g_W1H);
    cudaGetSymbolAddress((void**)&pW1L, g_W1L);
    cudaGetSymbolAddress((void**)&pW2H, g_W2H);
    cudaGetSymbolAddress((void**)&pW2L, g_W2L);

    cudaFuncSetAttribute((const void*)mma_gemm<128, 1>,
                         cudaFuncAttributeMaxDynamicSharedMemorySize, SMEM_BYTES);
    cudaFuncSetAttribute((const void*)mma_gemm<256, 2>,
                         cudaFuncAttributeMaxDynamicSharedMemorySize, SMEM_BYTES);
    cudaFuncSetAttribute((const void*)mma_gemm<128, 3>,
                         cudaFuncAttributeMaxDynamicSharedMemorySize, SMEM_BYTES);

    // 1. zero hagg / exsum
    init_kernel<<<(N * HDIM + 255) / 256, 256>>>(N);

    // 2. EK/EV/ebias -> combined small matrices + all bf16 splits (one kernel)
    etype_v2<<<ET, 128>>>(edge_emb, Wk, Wv, Web, beb);
    combo_v3<<<524, 128>>>(Wq, bq, Wk, bk, Wv, bv, W1, b1, W2);

    // 3. Q' GEMM with fused QEK side-output
    int gemm_blocks = (N + BM - 1) / BM;
    mma_gemm<128, 1><<<gemm_blocks, 256, SMEM_BYTES>>>(
        hidden, nullptr, nullptr, pWpH, pWpL, pbp, pQp, nullptr, nullptr, nullptr, N);

    // 4. fused edge pass (2 edges per warp)
    int edge_blocks = (E + 15) / 16;
    edge_fused_kernel<<<edge_blocks, 256>>>(hidden, src, tgt, etype, E);

    // 5. normalize: wex + AGG bf16 split
    normalize_kernel<<<(N + 7) / 8, 256>>>(N);

    // 6. FFN1 -> T (bf16 hi/lo)
    mma_gemm<256, 2><<<gemm_blocks, 256, SMEM_BYTES>>>(
        hidden, pAhi, pAlo, pW1H, pW1L, pb1t, nullptr, nullptr, nullptr, nullptr, N);

    // 7. FFN2 + residual + layernorm -> out
    mma_gemm<128, 3><<<gemm_blocks, 256, SMEM_BYTES>>>(
        nullptr, pThi, pTlo, pW2H, pW2L, b2, out, hidden, gamma, beta, N);
}

// round 17
// speedup vs baseline: 1.0154x; 1.0082x over previous
#include <cuda_runtime.h>
#include <cuda_bf16.h>
#include <math.h>

// Problem constants (B=1, N=50000, E=600000, H=128, ET=8)
#define NMAX 50000
#define EMAX 600000
#define HDIM 128
#define ETMAX 8

// ---------------- scratch ----------------
__device__ float g_Qp[NMAX * HDIM];     // Q' = scale*q @ Wk^T
__device__ float g_hagg[NMAX * HDIM];   // sum of ex * hidden[src]
__device__ float g_QEK[NMAX * ETMAX];   // scale*q.(EK[ty]+bk) + ebias[ty]
__device__ float g_exsum[NMAX * ETMAX];
__device__ float g_wex[NMAX * ETMAX];
__device__ float g_EK[ETMAX * HDIM];
__device__ float g_EV[ETMAX * HDIM];
__device__ float g_ebias[ETMAX];
__device__ float g_bp[HDIM];
__device__ float g_cbias[ETMAX];
__device__ float g_EVW[ETMAX * HDIM];   // EV @ W1[128:256]
__device__ float g_b1t[HDIM];           // b1 + bv @ W1[128:256]

// pre-split bf16 hi/lo operands (k-loop is conversion-free for these)
__device__ __nv_bfloat16 g_Ahi[NMAX * HDIM], g_Alo[NMAX * HDIM];   // hagg*invsm
__device__ __nv_bfloat16 g_Thi[NMAX * HDIM], g_Tlo[NMAX * HDIM];   // FFN1 out
__device__ __nv_bfloat16 g_WpH[HDIM * HDIM], g_WpL[HDIM * HDIM];
__device__ __nv_bfloat16 g_W1H[2 * HDIM * HDIM], g_W1L[2 * HDIM * HDIM]; // W1top ⊕ WvW1
__device__ __nv_bfloat16 g_W2H[HDIM * HDIM], g_W2L[HDIM * HDIM];
__device__ __nv_bfloat16 g_QEH[HDIM * ETMAX], g_QEL[HDIM * ETMAX];

#define SCALE 0.08838834764831845f  // 1/sqrt(128)

// ---------------- helpers ----------------
__device__ __forceinline__ unsigned pack_bf16(__nv_bfloat16 lo_k, __nv_bfloat16 hi_k) {
    return ((unsigned)__bfloat16_as_ushort(hi_k) << 16) | (unsigned)__bfloat16_as_ushort(lo_k);
}
__device__ __forceinline__ void split_bf16(float v, __nv_bfloat16& hi, __nv_bfloat16& lo) {
    hi = __float2bfloat16(v);
    lo = __float2bfloat16(v - __bfloat162float(hi));
}
__device__ __forceinline__ void mma_bf16(float c[4], const unsigned a[4], const unsigned b[2]) {
    asm volatile(
        "mma.sync.aligned.m16n8k16.row.col.f32.bf16.bf16.f32 "
        "{%0,%1,%2,%3}, {%4,%5,%6,%7}, {%8,%9}, {%0,%1,%2,%3};"
        : "+f"(c[0]), "+f"(c[1]), "+f"(c[2]), "+f"(c[3])
        : "r"(a[0]), "r"(a[1]), "r"(a[2]), "r"(a[3]), "r"(b[0]), "r"(b[1]));
}
__device__ __forceinline__ void ldsm_x4(unsigned r[4], unsigned addr) {
    asm volatile("ldmatrix.sync.aligned.m8n8.x4.shared.b16 {%0,%1,%2,%3}, [%4];"
                 : "=r"(r[0]), "=r"(r[1]), "=r"(r[2]), "=r"(r[3]) : "r"(addr));
}
__device__ __forceinline__ void ldsm_x4_t(unsigned r[4], unsigned addr) {
    asm volatile("ldmatrix.sync.aligned.m8n8.x4.trans.shared.b16 {%0,%1,%2,%3}, [%4];"
                 : "=r"(r[0]), "=r"(r[1]), "=r"(r[2]), "=r"(r[3]) : "r"(addr));
}

// ---------------- init: hagg=0, exsum=0 ----------------
__global__ void init_kernel(int Nn) {
    int i = blockIdx.x * blockDim.x + threadIdx.x;
    if (i < Nn * HDIM) g_hagg[i] = 0.0f;
    if (i < Nn * ETMAX) g_exsum[i] = 0.0f;
}

// ---------------- EK/EV/ebias: block per edge type ----------------
__global__ void etype_v2(const float* __restrict__ edge_emb,
                         const float* __restrict__ Wk,
                         const float* __restrict__ Wv,
                         const float* __restrict__ Web,
                         const float* __restrict__ beb) {
    __shared__ float eh[HDIM];
    int ty = blockIdx.x, j = threadIdx.x;
    eh[j] = edge_emb[ty * HDIM + j];
    __syncthreads();
    float k0 = 0, k1 = 0, k2 = 0, k3 = 0;
    float v0 = 0, v1 = 0, v2 = 0, v3 = 0;
#pragma unroll 8
    for (int k = 0; k < HDIM; k += 4) {
        k0 = fmaf(eh[k],     Wk[(k)     * HDIM + j], k0);
        k1 = fmaf(eh[k + 1], Wk[(k + 1) * HDIM + j], k1);
        k2 = fmaf(eh[k + 2], Wk[(k + 2) * HDIM + j], k2);
        k3 = fmaf(eh[k + 3], Wk[(k + 3) * HDIM + j], k3);
        v0 = fmaf(eh[k],     Wv[(k)     * HDIM + j], v0);
        v1 = fmaf(eh[k + 1], Wv[(k + 1) * HDIM + j], v1);
        v2 = fmaf(eh[k + 2], Wv[(k + 2) * HDIM + j], v2);
        v3 = fmaf(eh[k + 3], Wv[(k + 3) * HDIM + j], v3);
    }
    g_EK[ty * HDIM + j] = (k0 + k1) + (k2 + k3);
    g_EV[ty * HDIM + j] = (v0 + v1) + (v2 + v3);
    if (j == 0) {
        float a0 = 0, a1 = 0, a2 = 0, a3 = 0;
        for (int k = 0; k < HDIM; k += 4) {
            a0 = fmaf(eh[k], Web[k], a0);
            a1 = fmaf(eh[k + 1], Web[k + 1], a1);
            a2 = fmaf(eh[k + 2], Web[k + 2], a2);
            a3 = fmaf(eh[k + 3], Web[k + 3], a3);
        }
        g_ebias[ty] = (a0 + a1) + (a2 + a3) + beb[0];
    }
}

// ---------------- combined precompute v3: fuses all bf16 splits ----------------
// blocks:
//   [0,128)    : WpH/L row m        = split(SCALE * Wq[m,:] @ Wk^T)
//   [128,256)  : W1H/L row (128+m)  = split(Wv[m,:] @ W1b)
//   256        : bp                 (fp32)
//   257        : b1t                (fp32)
//   [258,266)  : EVW row            (fp32)
//   266        : QEH/L              = split(SCALE * Wq @ (EK+bk)^T)
//   267        : cbias              (fp32)
//   [268,396)  : W1H/L row r=b-268  = split(W1[r,:])
//   [396,524)  : W2H/L row r=b-396  = split(W2[r,:])
__global__ void combo_v3(const float* __restrict__ Wq, const float* __restrict__ bq,
                         const float* __restrict__ Wk, const float* __restrict__ bk,
                         const float* __restrict__ Wv, const float* __restrict__ bv,
                         const float* __restrict__ W1, const float* __restrict__ b1,
                         const float* __restrict__ W2) {
    __shared__ float row[HDIM];
    int b = blockIdx.x, t = threadIdx.x;
    const float* W1b = W1 + HDIM * HDIM;  // rows 128..255

    if (b >= 268) {
        // pure weight splits
        float v;
        __nv_bfloat16 *dh, *dl;
        int o;
        if (b < 396) { int r = b - 268; v = W1[r * HDIM + t]; dh = g_W1H; dl = g_W1L; o = r * HDIM + t; }
        else         { int r = b - 396; v = W2[r * HDIM + t]; dh = g_W2H; dl = g_W2L; o = r * HDIM + t; }
        __nv_bfloat16 hi, lo;
        split_bf16(v, hi, lo);
        dh[o] = hi; dl[o] = lo;
        return;
    }

    if (b < 128 || b == 256) {
        row[t] = (b < 128) ? Wq[b * HDIM + t] : bq[t];
        __syncthreads();
        const float4* wr = (const float4*)(Wk + t * HDIM);
        float a0 = 0, a1 = 0, a2 = 0, a3 = 0;
#pragma unroll 8
        for (int j = 0; j < 32; j++) {
            float4 w = wr[j];
            float4 q = *(const float4*)&row[j * 4];
            a0 = fmaf(q.x, w.x, a0);
            a1 = fmaf(q.y, w.y, a1);
            a2 = fmaf(q.z, w.z, a2);
            a3 = fmaf(q.w, w.w, a3);
        }
        float s = ((a0 + a1) + (a2 + a3)) * SCALE;
        if (b < 128) {
            __nv_bfloat16 hi, lo;
            split_bf16(s, hi, lo);
            g_WpH[b * HDIM + t] = hi;
            g_WpL[b * HDIM + t] = lo;
        } else g_bp[t] = s;
    } else if (b < 256 || b == 257 || (b >= 258 && b < 266)) {
        if (b < 256) row[t] = Wv[(b - 128) * HDIM + t];
        else if (b == 257) row[t] = bv[t];
        else row[t] = g_EV[(b - 258) * HDIM + t];
        __syncthreads();
        float a0 = 0, a1 = 0, a2 = 0, a3 = 0;
#pragma unroll 8
        for (int k = 0; k < HDIM; k += 4) {
            a0 = fmaf(row[k],     W1b[(k)     * HDIM + t], a0);
            a1 = fmaf(row[k + 1], W1b[(k + 1) * HDIM + t], a1);
            a2 = fmaf(row[k + 2], W1b[(k + 2) * HDIM + t], a2);
            a3 = fmaf(row[k + 3], W1b[(k + 3) * HDIM + t], a3);
        }
        float s = (a0 + a1) + (a2 + a3);
        if (b < 256) {
            int o = (HDIM + (b - 128)) * HDIM + t;   // bottom half of merged W1
            __nv_bfloat16 hi, lo;
            split_bf16(s, hi, lo);
            g_W1H[o] = hi;
            g_W1L[o] = lo;
        } else if (b == 257) g_b1t[t] = s + b1[t];
        else g_EVW[(b - 258) * HDIM + t] = s;
    } else if (b == 266) {
        row[t] = bk[t];
        __syncthreads();
        float acc[ETMAX] = {};
        const float4* qr = (const float4*)(Wq + t * HDIM);
#pragma unroll 4
        for (int j4 = 0; j4 < 32; j4++) {
            float4 q = qr[j4];
            float4 bb = *(const float4*)&row[j4 * 4];
#pragma unroll
            for (int ty = 0; ty < ETMAX; ty++) {
                float4 ek = *(const float4*)&g_EK[ty * HDIM + j4 * 4];
                acc[ty] += q.x * (ek.x + bb.x) + q.y * (ek.y + bb.y)
                         + q.z * (ek.z + bb.z) + q.w * (ek.w + bb.w);
            }
        }
#pragma unroll
        for (int ty = 0; ty < ETMAX; ty++) {
            __nv_bfloat16 hi, lo;
            split_bf16(acc[ty] * SCALE, hi, lo);
            g_QEH[t * ETMAX + ty] = hi;
            g_QEL[t * ETMAX + ty] = lo;
        }
    } else {
        if (t < ETMAX) {
            float a0 = 0, a1 = 0, a2 = 0, a3 = 0;
            for (int j = 0; j < HDIM; j += 4) {
                a0 = fmaf(bq[j],     g_EK[t * HDIM + j]     + bk[j],     a0);
                a1 = fmaf(bq[j + 1], g_EK[t * HDIM + j + 1] + bk[j + 1], a1);
                a2 = fmaf(bq[j + 2], g_EK[t * HDIM + j + 2] + bk[j + 2], a2);
                a3 = fmaf(bq[j + 3], g_EK[t * HDIM + j + 3] + bk[j + 3], a3);
            }
            g_cbias[t] = ((a0 + a1) + (a2 + a3)) * SCALE + g_ebias[t];
        }
    }
}

// ---------------- bf16x2 tensor-core GEMM, BK=64, ldmatrix, pre-split B ----------------
// MODE 1: Q' GEMM (A=hidden fp32-split) + QEK side-output.
// MODE 2: FFN1 (A k<128: hidden fp32-split; k>=128: pre-split AGG; W=g_W1 256 rows;
//         +wex@EVW, silu) -> writes T as bf16 hi/lo.
// MODE 3: FFN2 (A=T pre-split) + residual + layernorm -> out.
constexpr int BM = 64, BN = 128, BK = 64;
constexpr int LDK = BK + 8;   // 72 bf16 -> 144 B rows
constexpr int LDN = BN + 8;   // 136 bf16 -> 272 B rows

constexpr int OFF_A_HI = 0;                       // bf16 [64][72] = 9216
constexpr int OFF_A_LO = 9216;
constexpr int OFF_B_HI = 18432;                   // bf16 [64][136] = 17408
constexpr int OFF_B_LO = 35840;
constexpr int OFF_QE_HI = 53248;                  // bf16 [64][8] = 1024 (MODE 1)
constexpr int OFF_QE_LO = 54272;
constexpr int OFF_EVW  = 53248;                   // float [8][128] = 4096 (MODE 2)
constexpr int OFF_WEX  = 57344;                   // float [64][8] = 2048 (MODE 2)
constexpr int SMEM_BYTES = 61440;
// MODE 3 epilogue aliases [0, 32768) as float Us[64][128].

template <int KDIM, int MODE>
__global__ void __launch_bounds__(256, 2)
mma_gemm(const float* __restrict__ A,
         const __nv_bfloat16* __restrict__ AH, const __nv_bfloat16* __restrict__ AL,
         const __nv_bfloat16* __restrict__ WH, const __nv_bfloat16* __restrict__ WL,
         const float* __restrict__ bias,
         float* __restrict__ C,
         const float* __restrict__ hidden, const float* __restrict__ gamma,
         const float* __restrict__ beta,
         int M) {
    extern __shared__ char dynsmem[];
    __nv_bfloat16* As_hi = (__nv_bfloat16*)(dynsmem + OFF_A_HI);
    __nv_bfloat16* As_lo = (__nv_bfloat16*)(dynsmem + OFF_A_LO);
    __nv_bfloat16* Bs_hi = (__nv_bfloat16*)(dynsmem + OFF_B_HI);
    __nv_bfloat16* Bs_lo = (__nv_bfloat16*)(dynsmem + OFF_B_LO);
    __nv_bfloat16* QE_hi = (__nv_bfloat16*)(dynsmem + OFF_QE_HI);
    __nv_bfloat16* QE_lo = (__nv_bfloat16*)(dynsmem + OFF_QE_LO);
    float* evws = (float*)(dynsmem + OFF_EVW);
    float* wexs = (float*)(dynsmem + OFF_WEX);
    float* Us   = (float*)dynsmem;

    const int t = threadIdx.x;
    const int block_m = blockIdx.x * BM;
    const int lane = t & 31;
    const int wid = t >> 5;
    const int warp_m = (wid >> 2) * 32;
    const int warp_n = (wid & 3) * 32;
    const int lg = lane >> 2;
    const int lt = lane & 3;

    if (MODE == 2) {
        {
            int ty = t >> 5, n4 = (t & 31) * 4;
            *(float4*)&evws[ty * HDIM + n4] = *(const float4*)(g_EVW + ty * HDIM + n4);
        }
        if (t < 128) {
            int r = t >> 1, half = t & 1;
            int gm = block_m + r;
            float4 v = make_float4(0.f, 0.f, 0.f, 0.f);
            if (gm < M) v = *(const float4*)(g_wex + gm * ETMAX + half * 4);
            *(float4*)&wexs[r * ETMAX + half * 4] = v;
        }
    }

    // ---- ldmatrix per-lane base addresses ----
    unsigned sb = (unsigned)__cvta_generic_to_shared(dynsmem);
    unsigned a_addr0 = sb + OFF_A_HI + (warp_m + (lane & 15)) * (LDK * 2) + ((lane >> 4) * 8) * 2;
    unsigned a_addr1 = a_addr0 + 16 * (LDK * 2);
    unsigned b_row = ((lane & 7) + ((lane >> 3) & 1) * 8);
    unsigned b_addr0 = sb + OFF_B_HI + b_row * (LDN * 2) + (warp_n + (lane >> 4) * 8) * 2;
    unsigned b_addr1 = b_addr0 + 16 * 2;
    constexpr unsigned A_LO_D = OFF_A_LO - OFF_A_HI;
    constexpr unsigned B_LO_D = OFF_B_LO - OFF_B_HI;

    float acc[2][4][4];
#pragma unroll
    for (int mi = 0; mi < 2; mi++)
#pragma unroll
        for (int ni = 0; ni < 4; ni++)
#pragma unroll
            for (int r = 0; r < 4; r++) acc[mi][ni][r] = 0.0f;

    float acc_q[2][4];
    if (MODE == 1) {
#pragma unroll
        for (int mi = 0; mi < 2; mi++)
#pragma unroll
            for (int r = 0; r < 4; r++) acc_q[mi][r] = 0.0f;
    }

    for (int k0 = 0; k0 < KDIM; k0 += BK) {
        // ---- A tile ----
        if (MODE == 3 || (MODE == 2 && k0 >= HDIM)) {
            int colbase = (MODE == 3) ? k0 : (k0 - HDIM);
#pragma unroll
            for (int i = 0; i < 2; i++) {
                int idx = t + i * 256;
                int m = idx >> 3;
                int k8 = (idx & 7) * 8;
                int gm = block_m + m;
                uint4 vh = make_uint4(0, 0, 0, 0), vl = make_uint4(0, 0, 0, 0);
                if (gm < M) {
                    vh = *(const uint4*)(AH + (size_t)gm * HDIM + colbase + k8);
                    vl = *(const uint4*)(AL + (size_t)gm * HDIM + colbase + k8);
                }
                *(uint4*)&As_hi[m * LDK + k8] = vh;
                *(uint4*)&As_lo[m * LDK + k8] = vl;
            }
        } else {
#pragma unroll
            for (int i = 0; i < 4; i++) {
                int idx = t + i * 256;
                int m = idx >> 4;
                int k4 = (idx & 15) * 4;
                int gm = block_m + m;
                float4 v = make_float4(0.f, 0.f, 0.f, 0.f);
                if (gm < M) v = *(const float4*)(A + (size_t)gm * HDIM + k0 + k4);
                __nv_bfloat16 hx, lx, hy, ly, hz, lz, hw, lw;
                split_bf16(v.x, hx, lx); split_bf16(v.y, hy, ly);
                split_bf16(v.z, hz, lz); split_bf16(v.w, hw, lw);
                *(uint2*)&As_hi[m * LDK + k4] = make_uint2(pack_bf16(hx, hy), pack_bf16(hz, hw));
                *(uint2*)&As_lo[m * LDK + k4] = make_uint2(pack_bf16(lx, ly), pack_bf16(lz, lw));
            }
        }
        // ---- B tile: pre-split bf16, pure copy ----
#pragma unroll
        for (int i = 0; i < 4; i++) {
            int idx = t + i * 256;
            int kk = idx >> 4;
            int n8 = (idx & 15) * 8;
            size_t off = (size_t)(k0 + kk) * BN + n8;
            *(uint4*)&Bs_hi[kk * LDN + n8] = *(const uint4*)(WH + off);
            *(uint4*)&Bs_lo[kk * LDN + n8] = *(const uint4*)(WL + off);
        }
        // ---- WqEK tile (MODE 1) ----
        if (MODE == 1 && t < 128) {
            int h = t >> 6;     // 0 = hi, 1 = lo
            int c = t & 63;
            const __nv_bfloat16* s = (h ? g_QEL : g_QEH) + (size_t)(k0 + c) * ETMAX;
            __nv_bfloat16* d = (h ? QE_lo : QE_hi) + c * 8;
            *(uint4*)d = *(const uint4*)s;
        }
        __syncthreads();

#pragma unroll
        for (int ks = 0; ks < BK; ks += 16) {
            unsigned ah[2][4], al[2][4], bh[4][2], bl[4][2];
            ldsm_x4(ah[0], a_addr0 + ks * 2);
            ldsm_x4(ah[1], a_addr1 + ks * 2);
            ldsm_x4(al[0], a_addr0 + A_LO_D + ks * 2);
            ldsm_x4(al[1], a_addr1 + A_LO_D + ks * 2);
            {
                unsigned q[4];
                ldsm_x4_t(q, b_addr0 + ks * (LDN * 2));
                bh[0][0] = q[0]; bh[0][1] = q[1]; bh[1][0] = q[2]; bh[1][1] = q[3];
                ldsm_x4_t(q, b_addr1 + ks * (LDN * 2));
                bh[2][0] = q[0]; bh[2][1] = q[1]; bh[3][0] = q[2]; bh[3][1] = q[3];
                ldsm_x4_t(q, b_addr0 + B_LO_D + ks * (LDN * 2));
                bl[0][0] = q[0]; bl[0][1] = q[1]; bl[1][0] = q[2]; bl[1][1] = q[3];
                ldsm_x4_t(q, b_addr1 + B_LO_D + ks * (LDN * 2));
                bl[2][0] = q[0]; bl[2][1] = q[1]; bl[3][0] = q[2]; bl[3][1] = q[3];
            }
#pragma unroll
            for (int mi = 0; mi < 2; mi++)
#pragma unroll
                for (int ni = 0; ni < 4; ni++) {
                    mma_bf16(acc[mi][ni], ah[mi], bl[ni]);
                    mma_bf16(acc[mi][ni], al[mi], bh[ni]);
                    mma_bf16(acc[mi][ni], ah[mi], bh[ni]);
                }
            if (MODE == 1 && warp_n == 0) {
                unsigned qh[2], ql[2];
                int k = ks + lt * 2;
                qh[0] = pack_bf16(QE_hi[k * 8 + lg], QE_hi[(k + 1) * 8 + lg]);
                qh[1] = pack_bf16(QE_hi[(k + 8) * 8 + lg], QE_hi[(k + 9) * 8 + lg]);
                ql[0] = pack_bf16(QE_lo[k * 8 + lg], QE_lo[(k + 1) * 8 + lg]);
                ql[1] = pack_bf16(QE_lo[(k + 8) * 8 + lg], QE_lo[(k + 9) * 8 + lg]);
#pragma unroll
                for (int mi = 0; mi < 2; mi++) {
                    mma_bf16(acc_q[mi], ah[mi], ql);
                    mma_bf16(acc_q[mi], al[mi], qh);
                    mma_bf16(acc_q[mi], ah[mi], qh);
                }
            }
        }
        __syncthreads();
    }

    // ---- epilogue ----
    if (MODE == 1) {
#pragma unroll
        for (int mi = 0; mi < 2; mi++)
#pragma unroll
            for (int ni = 0; ni < 4; ni++) {
                int n = warp_n + ni * 8 + lt * 2;
                float b0 = bias[n], b1 = bias[n + 1];
#pragma unroll
                for (int h = 0; h < 2; h++) {
                    int gm = block_m + warp_m + mi * 16 + lg + h * 8;
                    if (gm >= M) continue;
                    *(float2*)(C + (size_t)gm * BN + n) =
                        make_float2(acc[mi][ni][2 * h] + b0, acc[mi][ni][2 * h + 1] + b1);
                }
            }
        if (warp_n == 0) {
            float cb0 = g_cbias[lt * 2], cb1 = g_cbias[lt * 2 + 1];
#pragma unroll
            for (int mi = 0; mi < 2; mi++)
#pragma unroll
                for (int h = 0; h < 2; h++) {
                    int gm = block_m + warp_m + mi * 16 + lg + h * 8;
                    if (gm >= M) continue;
                    *(float2*)(g_QEK + gm * ETMAX + lt * 2) =
                        make_float2(acc_q[mi][2 * h] + cb0, acc_q[mi][2 * h + 1] + cb1);
                }
        }
    } else if (MODE == 2) {
#pragma unroll
        for (int mi = 0; mi < 2; mi++)
#pragma unroll
            for (int ni = 0; ni < 4; ni++) {
                int n = warp_n + ni * 8 + lt * 2;
                float b0 = bias[n], b1 = bias[n + 1];
#pragma unroll
                for (int h = 0; h < 2; h++) {
                    int r = warp_m + mi * 16 + lg + h * 8;
                    int gm = block_m + r;
                    if (gm >= M) continue;
                    float v0 = acc[mi][ni][2 * h] + b0;
                    float v1 = acc[mi][ni][2 * h + 1] + b1;
#pragma unroll
                    for (int ty = 0; ty < ETMAX; ty++) {
                        float wv = wexs[r * ETMAX + ty];
                        v0 = fmaf(wv, evws[ty * HDIM + n], v0);
                        v1 = fmaf(wv, evws[ty * HDIM + n + 1], v1);
                    }
                    v0 = v0 / (1.0f + expf(-v0));
                    v1 = v1 / (1.0f + expf(-v1));
                    __nv_bfloat16 h0, l0, h1, l1;
                    split_bf16(v0, h0, l0);
                    split_bf16(v1, h1, l1);
                    *(unsigned*)&g_Thi[(size_t)gm * HDIM + n] = pack_bf16(h0, h1);
                    *(unsigned*)&g_Tlo[(size_t)gm * HDIM + n] = pack_bf16(l0, l1);
                }
            }
    } else {
        // FFN2 + residual + layernorm fused
#pragma unroll
        for (int mi = 0; mi < 2; mi++)
#pragma unroll
            for (int ni = 0; ni < 4; ni++) {
                int n = warp_n + ni * 8 + lt * 2;
                float b0 = bias[n], b1 = bias[n + 1];
#pragma unroll
                for (int h = 0; h < 2; h++) {
                    int r = warp_m + mi * 16 + lg + h * 8;
                    *(float2*)&Us[r * HDIM + n] =
                        make_float2(acc[mi][ni][2 * h] + b0, acc[mi][ni][2 * h + 1] + b1);
                }
            }
        __syncthreads();
        float4 gm4 = ((const float4*)gamma)[lane];
        float4 bt4 = ((const float4*)beta)[lane];
#pragma unroll
        for (int j = 0; j < 8; j++) {
            int r = wid * 8 + j;
            int gm = block_m + r;
            if (gm >= M) continue;
            float4 u = *(const float4*)&Us[r * HDIM + lane * 4];
            float4 hh = *(const float4*)(hidden + (size_t)gm * HDIM + lane * 4);
            float x0 = hh.x + u.x, x1 = hh.y + u.y, x2 = hh.z + u.z, x3 = hh.w + u.w;
            float sum = x0 + x1 + x2 + x3;
#pragma unroll
            for (int o = 16; o; o >>= 1) sum += __shfl_xor_sync(0xffffffffu, sum, o);
            float mu = sum * (1.0f / 128.0f);
            float d0 = x0 - mu, d1 = x1 - mu, d2 = x2 - mu, d3 = x3 - mu;
            float vs = d0 * d0 + d1 * d1 + d2 * d2 + d3 * d3;
#pragma unroll
            for (int o = 16; o; o >>= 1) vs += __shfl_xor_sync(0xffffffffu, vs, o);
            float inv = rsqrtf(vs * (1.0f / 128.0f) + 1e-5f);
            float4 o4;
            o4.x = d0 * inv * gm4.x + bt4.x;
            o4.y = d1 * inv * gm4.y + bt4.y;
            o4.z = d2 * inv * gm4.z + bt4.z;
            o4.w = d3 * inv * gm4.w + bt4.w;
            *(float4*)(C + (size_t)gm * HDIM + lane * 4) = o4;
        }
    }
}

// ---------------- fused edge pass: 2 edges per warp (16 lanes each) ----------------
__global__ void edge_fused_kernel(const float* __restrict__ hidden,
                                  const int* __restrict__ src, const int* __restrict__ tgt,
                                  const int* __restrict__ etype, int E) {
    int warp = blockIdx.x * 8 + (threadIdx.x >> 5);
    int half = (threadIdx.x >> 4) & 1;
    int e = warp * 2 + half;
    bool valid = (e < E);
    if (warp * 2 >= E) return;           // whole warp out of range
    int ec = valid ? e : (E - 1);        // clamp; predicated stores below
    int sl = threadIdx.x & 15;
    int s = src[ec], g = tgt[ec], ty = etype[ec];
    const float4* qr = (const float4*)(g_Qp + (size_t)g * HDIM);
    const float4* hr = (const float4*)(hidden + (size_t)s * HDIM);
    float4 q0 = qr[sl * 2], q1 = qr[sl * 2 + 1];
    float4 h0 = hr[sl * 2], h1 = hr[sl * 2 + 1];
    float d = q0.x * h0.x + q0.y * h0.y + q0.z * h0.z + q0.w * h0.w
            + q1.x * h1.x + q1.y * h1.y + q1.z * h1.z + q1.w * h1.w;
#pragma unroll
    for (int o = 8; o; o >>= 1) d += __shfl_xor_sync(0xffffffffu, d, o);
    float ex = expf(d + g_QEK[g * ETMAX + ty]);
    if (valid) {
        if (sl == 0) atomicAdd(&g_exsum[g * ETMAX + ty], ex);
        float* dst = g_hagg + (size_t)g * HDIM + sl * 8;
        asm volatile("red.global.add.v4.f32 [%0], {%1, %2, %3, %4};"
                     :: "l"(dst), "f"(ex * h0.x), "f"(ex * h0.y), "f"(ex * h0.z), "f"(ex * h0.w)
                     : "memory");
        asm volatile("red.global.add.v4.f32 [%0], {%1, %2, %3, %4};"
                     :: "l"(dst + 4), "f"(ex * h1.x), "f"(ex * h1.y), "f"(ex * h1.z), "f"(ex * h1.w)
                     : "memory");
    }
}

// ---------------- normalize: wex + AGG bf16 split (warp per node) ----------------
__global__ void normalize_kernel(int Nn) {
    int n = blockIdx.x * 8 + (threadIdx.x >> 5);
    if (n >= Nn) return;
    int lane = threadIdx.x & 31;
    float ex = (lane < ETMAX) ? g_exsum[n * ETMAX + lane] : 0.0f;
    float s = ex;
#pragma unroll
    for (int o = 4; o; o >>= 1) s += __shfl_xor_sync(0xffffffffu, s, o);
    s = __shfl_sync(0xffffffffu, s, 0);
    float inv = (s > 0.0f) ? (1.0f / s) : 0.0f;
    if (lane < ETMAX) g_wex[n * ETMAX + lane] = ex * inv;
    float4 v = ((const float4*)(g_hagg + (size_t)n * HDIM))[lane];
    v.x *= inv; v.y *= inv; v.z *= inv; v.w *= inv;
    __nv_bfloat16 hx, lx, hy, ly, hz, lz, hw, lw;
    split_bf16(v.x, hx, lx); split_bf16(v.y, hy, ly);
    split_bf16(v.z, hz, lz); split_bf16(v.w, hw, lw);
    ((uint2*)(g_Ahi + (size_t)n * HDIM))[lane] = make_uint2(pack_bf16(hx, hy), pack_bf16(hz, hw));
    ((uint2*)(g_Alo + (size_t)n * HDIM))[lane] = make_uint2(pack_bf16(lx, ly), pack_bf16(lz, lw));
}

// ---------------- launch ----------------
extern "C" void kernel_launch(void* const* d_in, const int* in_sizes, int n_in,
                              void* d_out, int out_size) {
    const float* hidden   = (const float*)d_in[0];
    const int*   edge_idx = (const int*)d_in[1];
    const int*   etype    = (const int*)d_in[2];
    const float* edge_emb = (const float*)d_in[3];
    const float* Wq = (const float*)d_in[4];
    const float* bq = (const float*)d_in[5];
    const float* Wk = (const float*)d_in[6];
    const float* bk = (const float*)d_in[7];
    const float* Wv = (const float*)d_in[8];
    const float* bv = (const float*)d_in[9];
    const float* Web = (const float*)d_in[10];
    const float* beb = (const float*)d_in[11];
    const float* W1 = (const float*)d_in[12];
    const float* b1 = (const float*)d_in[13];
    const float* W2 = (const float*)d_in[14];
    const float* b2 = (const float*)d_in[15];
    const float* gamma = (const float*)d_in[16];
    const float* beta  = (const float*)d_in[17];
    float* out = (float*)d_out;

    const int N  = in_sizes[0] / HDIM;
    const int E  = in_sizes[2];
    const int ET = in_sizes[3] / HDIM;
    const int* src = edge_idx;
    const int* tgt = edge_idx + E;

    float *pQp, *pbp, *pb1t;
    cudaGetSymbolAddress((void**)&pQp, g_Qp);
    cudaGetSymbolAddress((void**)&pbp, g_bp);
    cudaGetSymbolAddress((void**)&pb1t, g_b1t);
    __nv_bfloat16 *pAhi, *pAlo, *pThi, *pTlo, *pWpH, *pWpL, *pW1H, *pW1L, *pW2H, *pW2L;
    cudaGetSymbolAddress((void**)&pAhi, g_Ahi);
    cudaGetSymbolAddress((void**)&pAlo, g_Alo);
    cudaGetSymbolAddress((void**)&pThi, g_Thi);
    cudaGetSymbolAddress((void**)&pTlo, g_Tlo);
    cudaGetSymbolAddress((void**)&pWpH, g_WpH);
    cudaGetSymbolAddress((void**)&pWpL, g_WpL);
    cudaGetSymbolAddress((void**)&pW1H, g_W1H);
    cudaGetSymbolAddress((void**)&pW1L, g_W1L);
    cudaGetSymbolAddress((void**)&pW2H, g_W2H);
    cudaGetSymbolAddress((void**)&pW2L, g_W2L);

    cudaFuncSetAttribute((const void*)mma_gemm<128, 1>,
                         cudaFuncAttributeMaxDynamicSharedMemorySize, SMEM_BYTES);
    cudaFuncSetAttribute((const void*)mma_gemm<256, 2>,
                         cudaFuncAttributeMaxDynamicSharedMemorySize, SMEM_BYTES);
    cudaFuncSetAttribute((const void*)mma_gemm<128, 3>,
                         cudaFuncAttributeMaxDynamicSharedMemorySize, SMEM_BYTES);

    // 1. zero hagg / exsum
    init_kernel<<<(N * HDIM + 255) / 256, 256>>>(N);

    // 2. EK/EV/ebias -> combined small matrices + all bf16 splits (one kernel)
    etype_v2<<<ET, 128>>>(edge_emb, Wk, Wv, Web, beb);
    combo_v3<<<524, 128>>>(Wq, bq, Wk, bk, Wv, bv, W1, b1, W2);

    // 3. Q' GEMM with fused QEK side-output
    int gemm_blocks = (N + BM - 1) / BM;
    mma_gemm<128, 1><<<gemm_blocks, 256, SMEM_BYTES>>>(
        hidden, nullptr, nullptr, pWpH, pWpL, pbp, pQp, nullptr, nullptr, nullptr, N);

    // 4. fused edge pass (2 edges per warp)
    int edge_blocks = (E + 15) / 16;
    edge_fused_kernel<<<edge_blocks, 256>>>(hidden, src, tgt, etype, E);

    // 5. normalize: wex + AGG bf16 split
    normalize_kernel<<<(N + 7) / 8, 256>>>(N);

    // 6. FFN1 -> T (bf16 hi/lo)
    mma_gemm<256, 2><<<gemm_blocks, 256, SMEM_BYTES>>>(
        hidden, pAhi, pAlo, pW1H, pW1L, pb1t, nullptr, nullptr, nullptr, nullptr, N);

    // 7. FFN2 + residual + layernorm -> out
    mma_gemm<128, 3><<<gemm_blocks, 256, SMEM_BYTES>>>(
        nullptr, pThi, pTlo, pW2H, pW2L, b2, out, hidden, gamma, beta, N);
}